// round 9
// baseline (speedup 1.0000x reference)
#include <cuda_runtime.h>

// ---------------------------------------------------------------------------
// JEPAPointDecoder — full pipeline on GB300, fp32 with packed f32x2 FMA.
//
// Shapes: B=4, P=384, M=64, TOK=1024, C=128, R=12, k=8
//
// EdgeConv layer-1 factorization:  msg@We1 = a_i + b_j  with
//   a_i = x_i @ (We1_top - We1_bot) + be1,   b_j = x_j @ We1_bot
//
// R9: k_edge 256-thread (2 halves x 4 points, half the regs, 2x warps/SMSP);
// k_ab 4-row LDS.128 batches; kNN batch-of-8 candidates; launch order puts
// the new k_knn_batch<0> in the ncu-profiled slot (#4).
// ---------------------------------------------------------------------------

#define BB     4
#define PP     384
#define MMH    64
#define TOKN   1024
#define CC     128
#define RR     12
#define KK     8
#define NCTX   (PP*RR)        // 4608
#define NPRED  (MMH*RR)       // 768
#define NALL   (NCTX+NPRED)   // 5376
#define NC_TOT (BB*NCTX)      // 18432
#define NP_TOT (BB*NPRED)     // 3072
#define NA_TOT (BB*NALL)      // 21504

// ----------------------------- scratch ------------------------------------
__device__ float g_anchor[BB*3];
__device__ float g_ctx_feat[BB*PP*CC];
__device__ float g_pred_feat[BB*MMH*CC];
__device__ float g_xyz_ctx[NC_TOT*3];
__device__ float g_xyz_p[NP_TOT*3];
__device__ float g_xyz_all[NA_TOT*3];
__device__ float g_featAll[(size_t)NA_TOT*CC];
__device__ float g_a[(size_t)NA_TOT*CC];
__device__ float g_b[(size_t)NA_TOT*CC];
__device__ int   g_idx[NA_TOT*KK];
__device__ float g_Wab[131*256];
__device__ float g_bab[256];

// --------------------------- f32x2 primitives ------------------------------
typedef unsigned long long u64;

__device__ __forceinline__ void ffma2(u64& d, u64 a, u64 b) {
    asm("fma.rn.f32x2 %0, %1, %2, %0;" : "+l"(d) : "l"(a), "l"(b));
}
__device__ __forceinline__ u64 fma2v(u64 a, u64 b, u64 c) {
    u64 d;
    asm("fma.rn.f32x2 %0, %1, %2, %3;" : "=l"(d) : "l"(a), "l"(b), "l"(c));
    return d;
}
__device__ __forceinline__ u64 mulx2(u64 a, u64 b) {
    u64 d;
    asm("mul.rn.f32x2 %0, %1, %2;" : "=l"(d) : "l"(a), "l"(b));
    return d;
}
__device__ __forceinline__ u64 addx2(u64 a, u64 b) {
    u64 d;
    asm("add.rn.f32x2 %0, %1, %2;" : "=l"(d) : "l"(a), "l"(b));
    return d;
}
__device__ __forceinline__ u64 pack2(float lo, float hi) {
    u64 r;
    unsigned int a = __float_as_uint(lo), b = __float_as_uint(hi);
    asm("mov.b64 %0, {%1, %2};" : "=l"(r) : "r"(a), "r"(b));
    return r;
}
__device__ __forceinline__ float2 unpack2(u64 v) {
    unsigned int a, b;
    asm("mov.b64 {%0, %1}, %2;" : "=r"(a), "=r"(b) : "l"(v));
    return make_float2(__uint_as_float(a), __uint_as_float(b));
}

// ----------------------------- helpers ------------------------------------
template<int MODE>
__device__ __forceinline__ int mapOut(int i) {
    if (MODE == 0) return (i / NCTX)  * NALL + (i % NCTX);           // ctx
    if (MODE == 1) return (i / NPRED) * NALL + NCTX + (i % NPRED);   // pred
    return i;                                                        // global
}

__device__ __forceinline__ float sq3(float x, float y, float z) {
    return __fadd_rn(__fadd_rn(__fmul_rn(x, x), __fmul_rn(y, y)), __fmul_rn(z, z));
}

// ----------------------------- anchors ------------------------------------
__global__ void k_anchor(const float* __restrict__ ctx_xyz) {
    int b = blockIdx.x, tid = threadIdx.x;
    __shared__ float sred[3][128];
    float sx = 0.f, sy = 0.f, sz = 0.f;
    for (int p = tid; p < PP; p += 128) {
        const float* q = &ctx_xyz[(b * PP + p) * 3];
        sx += q[0]; sy += q[1]; sz += q[2];
    }
    sred[0][tid] = sx; sred[1][tid] = sy; sred[2][tid] = sz;
    __syncthreads();
    for (int s = 64; s > 0; s >>= 1) {
        if (tid < s) {
            sred[0][tid] += sred[0][tid + s];
            sred[1][tid] += sred[1][tid + s];
            sred[2][tid] += sred[2][tid + s];
        }
        __syncthreads();
    }
    if (tid == 0) {
        g_anchor[b * 3 + 0] = __fdiv_rn(sred[0][0], (float)PP);
        g_anchor[b * 3 + 1] = __fdiv_rn(sred[1][0], (float)PP);
        g_anchor[b * 3 + 2] = __fdiv_rn(sred[2][0], (float)PP);
    }
}

// --------------------------- token projection -----------------------------
template<int WHICH>
__global__ void k_proj(const float* __restrict__ tokens,
                       const float* __restrict__ Wp,
                       const float* __restrict__ bp) {
    constexpr int RPB = 8;
    __shared__ __align__(16) float st[RPB * TOKN];        // 32 KB
    float* out = (WHICH == 0) ? g_ctx_feat : g_pred_feat;
    int r0 = blockIdx.x * RPB;
    for (int e = threadIdx.x; e < RPB * TOKN; e += 128)
        st[e] = tokens[(size_t)r0 * TOKN + e];
    __syncthreads();
    int c = threadIdx.x;
    float bb = bp[c];
    u64 acc[RPB];
#pragma unroll
    for (int r = 0; r < RPB; ++r) acc[r] = pack2(bb, 0.f);
    for (int t = 0; t < TOKN; t += 4) {
        float w0 = Wp[(t + 0) * CC + c];
        float w1 = Wp[(t + 1) * CC + c];
        float w2 = Wp[(t + 2) * CC + c];
        float w3 = Wp[(t + 3) * CC + c];
        u64 ww01 = pack2(w0, w1);
        u64 ww23 = pack2(w2, w3);
#pragma unroll
        for (int r = 0; r < RPB; ++r) {
            ulonglong2 v = *(const ulonglong2*)&st[r * TOKN + t];
            ffma2(acc[r], v.x, ww01);
            ffma2(acc[r], v.y, ww23);
        }
    }
#pragma unroll
    for (int r = 0; r < RPB; ++r) {
        float2 u = unpack2(acc[r]);
        out[(size_t)(r0 + r) * CC + c] = u.x + u.y;
    }
}

// --------------------------- Wab construction -----------------------------
__global__ void k_wab(const float* __restrict__ We1, const float* __restrict__ be1) {
    int t = blockIdx.x * 256 + threadIdx.x;
    if (t < 131 * 128) {
        int r = t >> 7, c = t & 127;
        float top = We1[r * CC + c];
        float bot = We1[(131 + r) * CC + c];
        g_Wab[r * 256 + c]       = __fsub_rn(top, bot);
        g_Wab[r * 256 + 128 + c] = bot;
    }
    if (t < 128) { g_bab[t] = be1[t]; g_bab[128 + t] = 0.f; }
}

// ------------------------------ xyz builders ------------------------------
__global__ void k_xyz_ctx(const float* __restrict__ ctx_xyz,
                          const float* __restrict__ noise) {
    int i = blockIdx.x * 128 + threadIdx.x;
    if (i >= NC_TOT) return;
    float nx = noise[i * 3 + 0], ny = noise[i * 3 + 1], nz = noise[i * 3 + 2];
    float denom = __fadd_rn(sqrtf(sq3(nx, ny, nz)), 1e-6f);
    int bp = i / RR;
    g_xyz_ctx[i * 3 + 0] = __fadd_rn(ctx_xyz[bp * 3 + 0], __fmul_rn(__fdiv_rn(nx, denom), 0.02f));
    g_xyz_ctx[i * 3 + 1] = __fadd_rn(ctx_xyz[bp * 3 + 1], __fmul_rn(__fdiv_rn(ny, denom), 0.02f));
    g_xyz_ctx[i * 3 + 2] = __fadd_rn(ctx_xyz[bp * 3 + 2], __fmul_rn(__fdiv_rn(nz, denom), 0.02f));
}

__global__ void k_xyz_pred(const float* __restrict__ noise) {
    int i = blockIdx.x * 128 + threadIdx.x;
    if (i >= NP_TOT) return;
    float nx = noise[i * 3 + 0], ny = noise[i * 3 + 1], nz = noise[i * 3 + 2];
    float denom = __fadd_rn(sqrtf(sq3(nx, ny, nz)), 1e-6f);
    int b = i / NPRED;
    g_xyz_p[i * 3 + 0] = __fadd_rn(g_anchor[b * 3 + 0], __fmul_rn(__fdiv_rn(nx, denom), 0.05f));
    g_xyz_p[i * 3 + 1] = __fadd_rn(g_anchor[b * 3 + 1], __fmul_rn(__fdiv_rn(ny, denom), 0.05f));
    g_xyz_p[i * 3 + 2] = __fadd_rn(g_anchor[b * 3 + 2], __fmul_rn(__fdiv_rn(nz, denom), 0.05f));
}

// --------------------------------- kNN -------------------------------------
// SoA points in smem; f32x2-packed distance math; 64 queries x 8 slices;
// candidate batches of 8 with one min-precheck branch per batch.
// d2 rounding matches reference exactly; strict '<' ascending-j insertion
// preserves top_k tie-break.
template<int STAGE>  // 0: ctx (N=4608), 2: global (N=5376)
__global__ void __launch_bounds__(512) k_knn_batch() {
    constexpr int NB  = (STAGE == 0) ? NCTX : NALL;
    constexpr int QPB = 64;
    constexpr int NSL = 8;
    constexpr int SL  = NB / NSL;          // 576 / 672, both % 8 == 0, % 32 == 0
    extern __shared__ __align__(16) float smf[];
    float* sx_ = smf;
    float* sy_ = smf + NB;
    float* sz_ = smf + 2 * NB;
    float* sw_ = smf + 3 * NB;
    const float* xyz = (STAGE == 0) ? g_xyz_ctx : g_xyz_all;
    int b = blockIdx.y, base = b * NB;
    for (int j = threadIdx.x; j < NB; j += 512) {
        float x = xyz[(base + j) * 3 + 0];
        float y = xyz[(base + j) * 3 + 1];
        float z = xyz[(base + j) * 3 + 2];
        sx_[j] = x; sy_[j] = y; sz_[j] = z; sw_[j] = sq3(x, y, z);
    }
    __syncthreads();
    int qi = threadIdx.x & (QPB - 1);
    int slice = threadIdx.x / QPB;
    int q = blockIdx.x * QPB + qi;
    float qx = sx_[q], qy = sy_[q], qz = sz_[q], qw = sw_[q];
    u64 qxx = pack2(qx, qx), qyy = pack2(qy, qy), qzz = pack2(qz, qz);
    u64 qww = pack2(qw, qw);
    u64 neg2 = pack2(-2.f, -2.f);
    float bd[KK]; int bi[KK];
#pragma unroll
    for (int s = 0; s < KK; ++s) { bd[s] = 3.0e38f; bi[s] = 0; }

    auto ins = [&](float d2, int jj) {
        if (d2 < bd[KK - 1]) {
            int pos = KK - 1;
#pragma unroll
            for (int s = KK - 1; s > 0; --s)
                if (d2 < bd[s - 1]) { bd[s] = bd[s - 1]; bi[s] = bi[s - 1]; pos = s - 1; }
            bd[pos] = d2; bi[pos] = jj;
        }
    };

    int j0 = slice * SL, j1 = j0 + SL;
    // warp-uniform: SL % 32 == 0 and each warp covers a 32-aligned q range
    bool hasQ = (q >= j0) && (q < j1);

#define KNN_PAIRS(J)                                                             \
    ulonglong2 xxA = *(const ulonglong2*)&sx_[J];                                \
    ulonglong2 yyA = *(const ulonglong2*)&sy_[J];                                \
    ulonglong2 zzA = *(const ulonglong2*)&sz_[J];                                \
    ulonglong2 wwA = *(const ulonglong2*)&sw_[J];                                \
    ulonglong2 xxB = *(const ulonglong2*)&sx_[(J) + 4];                          \
    ulonglong2 yyB = *(const ulonglong2*)&sy_[(J) + 4];                          \
    ulonglong2 zzB = *(const ulonglong2*)&sz_[(J) + 4];                          \
    ulonglong2 wwB = *(const ulonglong2*)&sw_[(J) + 4];                          \
    u64 d0 = mulx2(qxx, xxA.x); d0 = fma2v(qyy, yyA.x, d0); d0 = fma2v(qzz, zzA.x, d0); \
    u64 d1 = mulx2(qxx, xxA.y); d1 = fma2v(qyy, yyA.y, d1); d1 = fma2v(qzz, zzA.y, d1); \
    u64 d2_ = mulx2(qxx, xxB.x); d2_ = fma2v(qyy, yyB.x, d2_); d2_ = fma2v(qzz, zzB.x, d2_); \
    u64 d3 = mulx2(qxx, xxB.y); d3 = fma2v(qyy, yyB.y, d3); d3 = fma2v(qzz, zzB.y, d3); \
    d0 = addx2(addx2(qww, wwA.x), mulx2(neg2, d0));                              \
    d1 = addx2(addx2(qww, wwA.y), mulx2(neg2, d1));                              \
    d2_ = addx2(addx2(qww, wwB.x), mulx2(neg2, d2_));                            \
    d3 = addx2(addx2(qww, wwB.y), mulx2(neg2, d3));                              \
    float2 pa = unpack2(d0), pb = unpack2(d1), pc = unpack2(d2_), pd = unpack2(d3);

    if (!hasQ) {
        for (int j = j0; j < j1; j += 8) {
            KNN_PAIRS(j)
            float m = fminf(fminf(fminf(pa.x, pa.y), fminf(pb.x, pb.y)),
                            fminf(fminf(pc.x, pc.y), fminf(pd.x, pd.y)));
            if (m < bd[KK - 1]) {
                ins(pa.x, j + 0); ins(pa.y, j + 1);
                ins(pb.x, j + 2); ins(pb.y, j + 3);
                ins(pc.x, j + 4); ins(pc.y, j + 5);
                ins(pd.x, j + 6); ins(pd.y, j + 7);
            }
        }
    } else {
        for (int j = j0; j < j1; j += 8) {
            KNN_PAIRS(j)
            if (j + 0 == q) pa.x = 3.0e38f;
            if (j + 1 == q) pa.y = 3.0e38f;
            if (j + 2 == q) pb.x = 3.0e38f;
            if (j + 3 == q) pb.y = 3.0e38f;
            if (j + 4 == q) pc.x = 3.0e38f;
            if (j + 5 == q) pc.y = 3.0e38f;
            if (j + 6 == q) pd.x = 3.0e38f;
            if (j + 7 == q) pd.y = 3.0e38f;
            float m = fminf(fminf(fminf(pa.x, pa.y), fminf(pb.x, pb.y)),
                            fminf(fminf(pc.x, pc.y), fminf(pd.x, pd.y)));
            if (m < bd[KK - 1]) {
                ins(pa.x, j + 0); ins(pa.y, j + 1);
                ins(pb.x, j + 2); ins(pb.y, j + 3);
                ins(pc.x, j + 4); ins(pc.y, j + 5);
                ins(pd.x, j + 6); ins(pd.y, j + 7);
            }
        }
    }
#undef KNN_PAIRS

    // ---- merge (buffers alias point arrays; scans done, sync-protected) ----
    __syncthreads();
    float* md = smf;                               // [NSL*KK][QPB] = 16 KB
    int*   mi = (int*)(smf + NSL * KK * QPB);      // 16 KB
#pragma unroll
    for (int s = 0; s < KK; ++s) {
        md[(slice * KK + s) * QPB + qi] = bd[s];
        mi[(slice * KK + s) * QPB + qi] = bi[s];
    }
    __syncthreads();
    if (slice == 0) {
        float fd[KK]; int fi[KK];
#pragma unroll
        for (int s = 0; s < KK; ++s) { fd[s] = 3.0e38f; fi[s] = 0; }
        for (int e = 0; e < NSL * KK; ++e) {        // slice-major = ascending j
            float d = md[e * QPB + qi];
            int  ix = mi[e * QPB + qi];
            if (d < fd[KK - 1]) {
                int pos = KK - 1;
#pragma unroll
                for (int s = KK - 1; s > 0; --s)
                    if (d < fd[s - 1]) { fd[s] = fd[s - 1]; fi[s] = fi[s - 1]; pos = s - 1; }
                fd[pos] = d; fi[pos] = ix;
            }
        }
#pragma unroll
        for (int s = 0; s < KK; ++s)
            g_idx[(base + q) * KK + s] = base + fi[s];
    }
}

// tiny 12-point graphs: one thread per query point
__global__ void k_knn_pred() {
    int i = blockIdx.x * 128 + threadIdx.x;
    if (i >= NP_TOT) return;
    int base = (i / RR) * RR;
    int lr = i - base;
    float qx = g_xyz_p[i * 3 + 0], qy = g_xyz_p[i * 3 + 1], qz = g_xyz_p[i * 3 + 2];
    float qsq = sq3(qx, qy, qz);
    float bd[KK]; int bi[KK];
#pragma unroll
    for (int s = 0; s < KK; ++s) { bd[s] = 3.0e38f; bi[s] = 0; }
    for (int j = 0; j < RR; ++j) {
        if (j == lr) continue;
        int jj = base + j;
        float px = g_xyz_p[jj * 3 + 0], py = g_xyz_p[jj * 3 + 1], pz = g_xyz_p[jj * 3 + 2];
        float psq = sq3(px, py, pz);
        float dot = __fmul_rn(qx, px);
        dot = __fmaf_rn(qy, py, dot);
        dot = __fmaf_rn(qz, pz, dot);
        float d2 = __fsub_rn(__fadd_rn(qsq, psq), __fmul_rn(2.0f, dot));
        if (d2 < bd[KK - 1]) {
            int pos = KK - 1;
#pragma unroll
            for (int s = KK - 1; s > 0; --s) {
                if (d2 < bd[s - 1]) { bd[s] = bd[s - 1]; bi[s] = bi[s - 1]; pos = s - 1; }
            }
            bd[pos] = d2; bi[pos] = j;
        }
    }
#pragma unroll
    for (int s = 0; s < KK; ++s)
        g_idx[i * KK + s] = base + bi[s];
}

// ------------------------- per-point a/b projection ------------------------
// 4-row batches via LDS.128: 16 loads + 32 ffma2 per 4 rows.
template<int MODE>   // 0 ctx, 1 pred, 2 global
__global__ void k_ab() {
    constexpr int PTS = 16;
    __shared__ __align__(16) float sx[PTS][132];
    const float* feat = (MODE == 0) ? g_ctx_feat : (MODE == 1) ? g_pred_feat : g_featAll;
    const float* xyz  = (MODE == 0) ? g_xyz_ctx  : (MODE == 1) ? g_xyz_p    : g_xyz_all;
    int i0 = blockIdx.x * PTS;
    for (int e = threadIdx.x; e < PTS * 131; e += 256) {
        int p = e / 131, t = e - p * 131;
        int i = i0 + p;
        int fr = (MODE == 2) ? i : (i / RR);
        sx[p][t] = (t < CC) ? feat[(size_t)fr * CC + t] : xyz[i * 3 + (t - CC)];
    }
    __syncthreads();
    int col = threadIdx.x;                // 0..255
    float bb = g_bab[col];
    u64 acc[PTS];
    float tacc[PTS];
    u64 init = pack2(bb, 0.f);
#pragma unroll
    for (int p = 0; p < PTS; ++p) { acc[p] = init; tacc[p] = 0.f; }
    for (int r = 0; r < 128; r += 4) {
        u64 ww01 = pack2(g_Wab[(r + 0) * 256 + col], g_Wab[(r + 1) * 256 + col]);
        u64 ww23 = pack2(g_Wab[(r + 2) * 256 + col], g_Wab[(r + 3) * 256 + col]);
#pragma unroll
        for (int p = 0; p < PTS; ++p) {
            ulonglong2 v = *(const ulonglong2*)&sx[p][r];
            ffma2(acc[p], v.x, ww01);
            ffma2(acc[p], v.y, ww23);
        }
    }
#pragma unroll
    for (int r = 128; r < 131; ++r) {
        float w = g_Wab[r * 256 + col];
#pragma unroll
        for (int p = 0; p < PTS; ++p) tacc[p] = fmaf(sx[p][r], w, tacc[p]);
    }
#pragma unroll
    for (int p = 0; p < PTS; ++p) {
        float2 u = unpack2(acc[p]);
        float res = u.x + u.y + tacc[p];
        int i = i0 + p;
        if (col < CC) g_a[(size_t)i * CC + col] = res;
        else          g_b[(size_t)i * CC + (col - CC)] = res;
    }
}

// --------------------- EdgeConv layer 2 + max aggregate --------------------
// out[i,c] = max_j ( relu(a_i + b_{n_j}) @ We2[:,c] ) + be2[c]
// 256 threads: c = tid&127, half = tid>>7 owns 4 of the 8 points.
// acc 16 u64 (32 regs) -> 2x warps/SMSP vs R8. LDS reads warp-broadcast.
template<int MODE>
__global__ void __launch_bounds__(256) k_edge(const float* __restrict__ We2,
                                              const float* __restrict__ be2) {
    constexpr int PTS = 8;
    __shared__ __align__(16) float shid[128 * 68];    // [h][e], stride 68
    int i0 = blockIdx.x * PTS;
    int c = threadIdx.x & 127, half = threadIdx.x >> 7;
#pragma unroll
    for (int p2 = 0; p2 < 4; ++p2) {
        int p = half * 4 + p2;
        int i = i0 + p;
        float av = g_a[(size_t)i * CC + c];
#pragma unroll
        for (int j = 0; j < KK; ++j) {
            int nb = g_idx[i * KK + j];
            float bv = g_b[(size_t)nb * CC + c];
            shid[c * 68 + p * KK + j] = fmaxf(__fadd_rn(av, bv), 0.f);
        }
    }
    __syncthreads();
    u64 acc[16];
#pragma unroll
    for (int e = 0; e < 16; ++e) acc[e] = 0ull;
    const float* wp_ = We2 + c;
#pragma unroll 2
    for (int h = 0; h < 128; ++h) {
        float w = wp_[h * CC];
        u64 ww = pack2(w, w);
        const ulonglong2* hp = (const ulonglong2*)&shid[h * 68 + half * 32];
#pragma unroll
        for (int e = 0; e < 8; ++e) {
            ulonglong2 v = hp[e];
            ffma2(acc[2 * e + 0], v.x, ww);
            ffma2(acc[2 * e + 1], v.y, ww);
        }
    }
    float bb = be2[c];
#pragma unroll
    for (int p2 = 0; p2 < 4; ++p2) {
        float2 v0 = unpack2(acc[p2 * 4 + 0]);
        float2 v1 = unpack2(acc[p2 * 4 + 1]);
        float2 v2 = unpack2(acc[p2 * 4 + 2]);
        float2 v3 = unpack2(acc[p2 * 4 + 3]);
        float mx = fmaxf(fmaxf(fmaxf(v0.x, v0.y), fmaxf(v1.x, v1.y)),
                         fmaxf(fmaxf(v2.x, v2.y), fmaxf(v3.x, v3.y)));
        g_featAll[(size_t)mapOut<MODE>(i0 + half * 4 + p2) * CC + c] = mx + bb;
    }
}

// ------------------------------ offset MLP ---------------------------------
template<int MODE>
__global__ void __launch_bounds__(128) k_offset(const float* __restrict__ W1,
                                                const float* __restrict__ b1,
                                                const float* __restrict__ W2,
                                                const float* __restrict__ b2,
                                                float* __restrict__ outp) {
    constexpr int PTS = 8;
    __shared__ __align__(16) float sf[PTS][CC];
    __shared__ float sh[PTS][CC];
    int i0 = blockIdx.x * PTS, tid = threadIdx.x;
#pragma unroll
    for (int p = 0; p < PTS; ++p)
        sf[p][tid] = g_featAll[(size_t)mapOut<MODE>(i0 + p) * CC + tid];
    __syncthreads();
    float bb = b1[tid];
    u64 acc[PTS];
    u64 init = pack2(bb, 0.f);
#pragma unroll
    for (int p = 0; p < PTS; ++p) acc[p] = init;
    for (int r = 0; r < CC; r += 2) {
        u64 ww = pack2(W1[(r + 0) * CC + tid], W1[(r + 1) * CC + tid]);
#pragma unroll
        for (int p = 0; p < PTS; ++p) {
            u64 v = *(const u64*)&sf[p][r];
            ffma2(acc[p], v, ww);
        }
    }
#pragma unroll
    for (int p = 0; p < PTS; ++p) {
        float2 u = unpack2(acc[p]);
        sh[p][tid] = fmaxf(u.x + u.y, 0.f);
    }
    __syncthreads();
    int wp0 = (tid >> 5) * 2, l = tid & 31;
#pragma unroll
    for (int t = 0; t < 2; ++t) {
        int wp = wp0 + t;
        int i = i0 + wp;
        float s0 = 0.f, s1 = 0.f, s2 = 0.f;
        for (int h = l; h < CC; h += 32) {
            float hv = sh[wp][h];
            s0 = fmaf(hv, W2[h * 3 + 0], s0);
            s1 = fmaf(hv, W2[h * 3 + 1], s1);
            s2 = fmaf(hv, W2[h * 3 + 2], s2);
        }
#pragma unroll
        for (int off = 16; off; off >>= 1) {
            s0 += __shfl_down_sync(0xffffffffu, s0, off);
            s1 += __shfl_down_sync(0xffffffffu, s1, off);
            s2 += __shfl_down_sync(0xffffffffu, s2, off);
        }
        if (l == 0) {
            const float* xin = (MODE == 0) ? g_xyz_ctx : (MODE == 1) ? g_xyz_p : g_xyz_all;
            float* orow;
            if (MODE == 2) orow = outp + (size_t)i * 3;
            else           orow = g_xyz_all + (size_t)mapOut<MODE>(i) * 3;
            orow[0] = xin[i * 3 + 0] + s0 + b2[0];
            orow[1] = xin[i * 3 + 1] + s1 + b2[1];
            orow[2] = xin[i * 3 + 2] + s2 + b2[2];
        }
    }
}

// ------------------------------- launcher ----------------------------------
extern "C" void kernel_launch(void* const* d_in, const int* in_sizes, int n_in,
                              void* d_out, int out_size) {
    const float* ctx_xyz     = (const float*)d_in[0];
    const float* ctx_tokens  = (const float*)d_in[1];
    const float* pred_tokens = (const float*)d_in[2];
    const float* noise_ctx   = (const float*)d_in[3];
    const float* noise_pred  = (const float*)d_in[4];
    const float* Wp  = (const float*)d_in[5];
    const float* bp  = (const float*)d_in[6];
    const float* We1 = (const float*)d_in[7];
    const float* be1 = (const float*)d_in[8];
    const float* We2 = (const float*)d_in[9];
    const float* be2 = (const float*)d_in[10];
    const float* Wc1 = (const float*)d_in[11];
    const float* bc1 = (const float*)d_in[12];
    const float* Wc2 = (const float*)d_in[13];
    const float* bc2 = (const float*)d_in[14];
    const float* Wq1 = (const float*)d_in[15];
    const float* bq1 = (const float*)d_in[16];
    const float* Wq2 = (const float*)d_in[17];
    const float* bq2 = (const float*)d_in[18];
    const float* Wf1 = (const float*)d_in[19];
    const float* bf1 = (const float*)d_in[20];
    const float* Wf2 = (const float*)d_in[21];
    const float* bf2 = (const float*)d_in[22];
    (void)in_sizes; (void)n_in; (void)out_size;
    float* out = (float*)d_out;

    constexpr int SM_KNN0 = NCTX * 16;   // 73728
    constexpr int SM_KNN2 = NALL * 16;   // 86016
    cudaFuncSetAttribute(k_knn_batch<0>, cudaFuncAttributeMaxDynamicSharedMemorySize, SM_KNN0);
    cudaFuncSetAttribute(k_knn_batch<2>, cudaFuncAttributeMaxDynamicSharedMemorySize, SM_KNN2);

    // launch 4 == ncu-captured slot -> k_knn_batch<0> this round
    k_xyz_ctx<<<NC_TOT / 128, 128>>>(ctx_xyz, noise_ctx);           // 1
    k_wab<<<(131 * 128 + 255) / 256, 256>>>(We1, be1);              // 2
    k_proj<0><<<BB * PP / 8, 128>>>(ctx_tokens, Wp, bp);            // 3
    k_knn_batch<0><<<dim3(NCTX / 64, BB), 512, SM_KNN0>>>();        // 4  (profiled)
    k_anchor<<<BB, 128>>>(ctx_xyz);                                 // 5
    k_xyz_pred<<<NP_TOT / 128, 128>>>(noise_pred);                  // 6
    k_proj<1><<<BB * MMH / 8, 128>>>(pred_tokens, Wp, bp);          // 7

    // ---- context branch ----
    k_ab<0><<<NC_TOT / 16, 256>>>();
    k_edge<0><<<NC_TOT / 8, 256>>>(We2, be2);
    k_offset<0><<<NC_TOT / 8, 128>>>(Wc1, bc1, Wc2, bc2, nullptr);

    // ---- prediction branch ----
    k_knn_pred<<<NP_TOT / 128, 128>>>();
    k_ab<1><<<NP_TOT / 16, 256>>>();
    k_edge<1><<<NP_TOT / 8, 256>>>(We2, be2);
    k_offset<1><<<NP_TOT / 8, 128>>>(Wq1, bq1, Wq2, bq2, nullptr);

    // ---- global refinement ----
    k_knn_batch<2><<<dim3(NALL / 64, BB), 512, SM_KNN2>>>();
    k_ab<2><<<NA_TOT / 16, 256>>>();
    k_edge<2><<<NA_TOT / 8, 256>>>(We2, be2);
    k_offset<2><<<NA_TOT / 8, 128>>>(Wf1, bf1, Wf2, bf2, out);
}

// round 13
// speedup vs baseline: 1.2794x; 1.2794x over previous
#include <cuda_runtime.h>

// ---------------------------------------------------------------------------
// JEPAPointDecoder — full pipeline on GB300, fp32 with packed f32x2 FMA.
//
// Shapes: B=4, P=384, M=64, TOK=1024, C=128, R=12, k=8
//
// EdgeConv layer-1 factorization:  msg@We1 = a_i + b_j  with
//   a_i = x_i @ (We1_top - We1_bot) + be1,   b_j = x_j @ We1_bot
//
// R10: brute-force kNN replaced by exact cluster-screened kNN.
// Points come in 12-replica clusters; per-query top-8 within own cluster
// gives a distance bound; triangle-inequality screening (conservative fp
// margins) selects candidate clusters; refinement uses the bit-identical
// reference d2 formula with (ordered-d2, index) lex keys so the neighbor
// SET exactly matches jax top_k regardless of scan order.
// ---------------------------------------------------------------------------

#define BB     4
#define PP     384
#define MMH    64
#define TOKN   1024
#define CC     128
#define RR     12
#define KK     8
#define NCTX   (PP*RR)        // 4608
#define NPRED  (MMH*RR)       // 768
#define NALL   (NCTX+NPRED)   // 5376
#define NC_TOT (BB*NCTX)      // 18432
#define NP_TOT (BB*NPRED)     // 3072
#define NA_TOT (BB*NALL)      // 21504
#define NCLMAX (NALL/12)      // 448 clusters per batch (global stage)
#define CAP    120            // cluster-list capacity (overflow -> fallback)

// ----------------------------- scratch ------------------------------------
__device__ float g_anchor[BB*3];
__device__ float g_ctx_feat[BB*PP*CC];
__device__ float g_pred_feat[BB*MMH*CC];
__device__ float g_xyz_ctx[NC_TOT*3];
__device__ float g_xyz_p[NP_TOT*3];
__device__ float g_xyz_all[NA_TOT*3];
__device__ float g_featAll[(size_t)NA_TOT*CC];
__device__ float g_a[(size_t)NA_TOT*CC];
__device__ float g_b[(size_t)NA_TOT*CC];
__device__ int   g_idx[NA_TOT*KK];
__device__ float g_Wab[131*256];
__device__ float g_bab[256];

typedef unsigned long long u64;
__device__ u64   g_keys[(size_t)NA_TOT*8];      // per-query top-8 lex keys
__device__ float g_ccen[BB*NCLMAX*3];
__device__ float g_crad[BB*NCLMAX];
__device__ float g_crq[BB*NCLMAX];
__device__ int   g_ccnt[BB*NCLMAX];
__device__ int   g_clist[BB*NCLMAX*CAP];

// --------------------------- f32x2 primitives ------------------------------
__device__ __forceinline__ void ffma2(u64& d, u64 a, u64 b) {
    asm("fma.rn.f32x2 %0, %1, %2, %0;" : "+l"(d) : "l"(a), "l"(b));
}
__device__ __forceinline__ u64 pack2(float lo, float hi) {
    u64 r;
    unsigned int a = __float_as_uint(lo), b = __float_as_uint(hi);
    asm("mov.b64 %0, {%1, %2};" : "=l"(r) : "r"(a), "r"(b));
    return r;
}
__device__ __forceinline__ float2 unpack2(u64 v) {
    unsigned int a, b;
    asm("mov.b64 {%0, %1}, %2;" : "=r"(a), "=r"(b) : "l"(v));
    return make_float2(__uint_as_float(a), __uint_as_float(b));
}

// ----------------------------- helpers ------------------------------------
template<int MODE>
__device__ __forceinline__ int mapOut(int i) {
    if (MODE == 0) return (i / NCTX)  * NALL + (i % NCTX);           // ctx
    if (MODE == 1) return (i / NPRED) * NALL + NCTX + (i % NPRED);   // pred
    return i;                                                        // global
}

__device__ __forceinline__ float sq3(float x, float y, float z) {
    return __fadd_rn(__fadd_rn(__fmul_rn(x, x), __fmul_rn(y, y)), __fmul_rn(z, z));
}

// order-preserving float->uint (monotone; -0 cannot occur for our d2)
__device__ __forceinline__ unsigned int ordf(float f) {
    unsigned int b = __float_as_uint(f);
    return (b & 0x80000000u) ? ~b : (b | 0x80000000u);
}
__device__ __forceinline__ float iordf(unsigned int h) {
    unsigned int b = (h & 0x80000000u) ? (h & 0x7FFFFFFFu) : ~h;
    return __uint_as_float(b);
}
__device__ __forceinline__ u64 dkey(float d2, int j) {
    return ((u64)ordf(d2) << 32) | (unsigned int)j;
}
// exact reference d2: sub(add(qw,pw), mul(2,dot)), dot = mul,fma,fma
__device__ __forceinline__ float refd2(float qx, float qy, float qz, float qw,
                                       float px, float py, float pz, float pw) {
    float dot = __fmul_rn(qx, px);
    dot = __fmaf_rn(qy, py, dot);
    dot = __fmaf_rn(qz, pz, dot);
    return __fsub_rn(__fadd_rn(qw, pw), __fmul_rn(2.0f, dot));
}
// sorted strict-< insert of key into ascending k[0..7]
#define KEY_INS(k, key) do {                                            \
    if ((key) < k[7]) {                                                 \
        int _pos = 7;                                                   \
        _Pragma("unroll")                                               \
        for (int _s = 7; _s > 0; --_s)                                  \
            if ((key) < k[_s - 1]) { k[_s] = k[_s - 1]; _pos = _s - 1; }\
        k[_pos] = (key);                                                \
    } } while (0)

// ----------------------------- anchors ------------------------------------
__global__ void k_anchor(const float* __restrict__ ctx_xyz) {
    int b = blockIdx.x, tid = threadIdx.x;
    __shared__ float sred[3][128];
    float sx = 0.f, sy = 0.f, sz = 0.f;
    for (int p = tid; p < PP; p += 128) {
        const float* q = &ctx_xyz[(b * PP + p) * 3];
        sx += q[0]; sy += q[1]; sz += q[2];
    }
    sred[0][tid] = sx; sred[1][tid] = sy; sred[2][tid] = sz;
    __syncthreads();
    for (int s = 64; s > 0; s >>= 1) {
        if (tid < s) {
            sred[0][tid] += sred[0][tid + s];
            sred[1][tid] += sred[1][tid + s];
            sred[2][tid] += sred[2][tid + s];
        }
        __syncthreads();
    }
    if (tid == 0) {
        g_anchor[b * 3 + 0] = __fdiv_rn(sred[0][0], (float)PP);
        g_anchor[b * 3 + 1] = __fdiv_rn(sred[1][0], (float)PP);
        g_anchor[b * 3 + 2] = __fdiv_rn(sred[2][0], (float)PP);
    }
}

// --------------------------- token projection -----------------------------
template<int WHICH>
__global__ void k_proj(const float* __restrict__ tokens,
                       const float* __restrict__ Wp,
                       const float* __restrict__ bp) {
    constexpr int RPB = 8;
    __shared__ __align__(16) float st[RPB * TOKN];        // 32 KB
    float* out = (WHICH == 0) ? g_ctx_feat : g_pred_feat;
    int r0 = blockIdx.x * RPB;
    for (int e = threadIdx.x; e < RPB * TOKN; e += 128)
        st[e] = tokens[(size_t)r0 * TOKN + e];
    __syncthreads();
    int c = threadIdx.x;
    float bb = bp[c];
    u64 acc[RPB];
#pragma unroll
    for (int r = 0; r < RPB; ++r) acc[r] = pack2(bb, 0.f);
    for (int t = 0; t < TOKN; t += 4) {
        float w0 = Wp[(t + 0) * CC + c];
        float w1 = Wp[(t + 1) * CC + c];
        float w2 = Wp[(t + 2) * CC + c];
        float w3 = Wp[(t + 3) * CC + c];
        u64 ww01 = pack2(w0, w1);
        u64 ww23 = pack2(w2, w3);
#pragma unroll
        for (int r = 0; r < RPB; ++r) {
            ulonglong2 v = *(const ulonglong2*)&st[r * TOKN + t];
            ffma2(acc[r], v.x, ww01);
            ffma2(acc[r], v.y, ww23);
        }
    }
#pragma unroll
    for (int r = 0; r < RPB; ++r) {
        float2 u = unpack2(acc[r]);
        out[(size_t)(r0 + r) * CC + c] = u.x + u.y;
    }
}

// --------------------------- Wab construction -----------------------------
__global__ void k_wab(const float* __restrict__ We1, const float* __restrict__ be1) {
    int t = blockIdx.x * 256 + threadIdx.x;
    if (t < 131 * 128) {
        int r = t >> 7, c = t & 127;
        float top = We1[r * CC + c];
        float bot = We1[(131 + r) * CC + c];
        g_Wab[r * 256 + c]       = __fsub_rn(top, bot);
        g_Wab[r * 256 + 128 + c] = bot;
    }
    if (t < 128) { g_bab[t] = be1[t]; g_bab[128 + t] = 0.f; }
}

// ------------------------------ xyz builders ------------------------------
__global__ void k_xyz_ctx(const float* __restrict__ ctx_xyz,
                          const float* __restrict__ noise) {
    int i = blockIdx.x * 128 + threadIdx.x;
    if (i >= NC_TOT) return;
    float nx = noise[i * 3 + 0], ny = noise[i * 3 + 1], nz = noise[i * 3 + 2];
    float denom = __fadd_rn(sqrtf(sq3(nx, ny, nz)), 1e-6f);
    int bp = i / RR;
    g_xyz_ctx[i * 3 + 0] = __fadd_rn(ctx_xyz[bp * 3 + 0], __fmul_rn(__fdiv_rn(nx, denom), 0.02f));
    g_xyz_ctx[i * 3 + 1] = __fadd_rn(ctx_xyz[bp * 3 + 1], __fmul_rn(__fdiv_rn(ny, denom), 0.02f));
    g_xyz_ctx[i * 3 + 2] = __fadd_rn(ctx_xyz[bp * 3 + 2], __fmul_rn(__fdiv_rn(nz, denom), 0.02f));
}

__global__ void k_xyz_pred(const float* __restrict__ noise) {
    int i = blockIdx.x * 128 + threadIdx.x;
    if (i >= NP_TOT) return;
    float nx = noise[i * 3 + 0], ny = noise[i * 3 + 1], nz = noise[i * 3 + 2];
    float denom = __fadd_rn(sqrtf(sq3(nx, ny, nz)), 1e-6f);
    int b = i / NPRED;
    g_xyz_p[i * 3 + 0] = __fadd_rn(g_anchor[b * 3 + 0], __fmul_rn(__fdiv_rn(nx, denom), 0.05f));
    g_xyz_p[i * 3 + 1] = __fadd_rn(g_anchor[b * 3 + 1], __fmul_rn(__fdiv_rn(ny, denom), 0.05f));
    g_xyz_p[i * 3 + 2] = __fadd_rn(g_anchor[b * 3 + 2], __fmul_rn(__fdiv_rn(nz, denom), 0.05f));
}

// ===================== cluster-screened exact kNN ==========================
// kA: own-cluster top-8 + cluster center/radius/query-bound
template<int STAGE>  // 0: ctx, 2: global
__global__ void __launch_bounds__(192) k_knn_own() {
    constexpr int NB  = (STAGE == 0) ? NCTX : NALL;
    constexpr int NCL = NB / 12;
    const float* xyz = (STAGE == 0) ? g_xyz_ctx : g_xyz_all;
    __shared__ float4 spt[192];
    __shared__ float sbd[192];
    int b = blockIdx.y, tid = threadIdx.x;
    int i0 = blockIdx.x * 192;
    int i = i0 + tid;                 // batch-local query
    int base = b * NB;
    {
        float x = xyz[(base + i) * 3 + 0];
        float y = xyz[(base + i) * 3 + 1];
        float z = xyz[(base + i) * 3 + 2];
        spt[tid] = make_float4(x, y, z, sq3(x, y, z));
    }
    __syncthreads();
    int lc = tid / 12, r = tid - lc * 12;
    int lbase = lc * 12;
    float4 pq = spt[tid];
    u64 k[8];
#pragma unroll
    for (int s = 0; s < 8; ++s) k[s] = 0xFFFFFFFFFFFFFFFFull;
#pragma unroll
    for (int jj = 0; jj < 12; ++jj) {
        if (jj == r) continue;
        float4 pj = spt[lbase + jj];
        float d2 = refd2(pq.x, pq.y, pq.z, pq.w, pj.x, pj.y, pj.z, pj.w);
        u64 key = dkey(d2, i0 + lbase + jj);
        KEY_INS(k, key);
    }
    size_t kb = ((size_t)base + i) * 8;
#pragma unroll
    for (int s = 0; s < 8; ++s) g_keys[kb + s] = k[s];
    sbd[tid] = iordf((unsigned int)(k[7] >> 32));   // bd7 (11 cands >= 8: filled)
    __syncthreads();
    if (r == 0) {
        float mb = 0.f, sx = 0.f, sy = 0.f, sz = 0.f;
        for (int t = 0; t < 12; ++t) {
            mb = fmaxf(mb, sbd[lbase + t]);
            float4 p = spt[lbase + t];
            sx += p.x; sy += p.y; sz += p.z;
        }
        float cx = sx / 12.f, cy = sy / 12.f, cz = sz / 12.f;
        float mr2 = 0.f;
        for (int t = 0; t < 12; ++t) {
            float4 p = spt[lbase + t];
            float dx = p.x - cx, dy = p.y - cy, dz = p.z - cz;
            mr2 = fmaxf(mr2, dx * dx + dy * dy + dz * dz);
        }
        int cg = b * NCL + i / 12;
        g_ccen[cg * 3 + 0] = cx; g_ccen[cg * 3 + 1] = cy; g_ccen[cg * 3 + 2] = cz;
        g_crad[cg] = sqrtf(mr2) * 1.0001f + 1e-5f;
        g_crq[cg]  = sqrtf(fmaxf(mb, 0.f)) * 1.0001f + 1e-5f;
    }
}

// kB: conservative cluster-pair screen -> per-cluster candidate list
template<int STAGE>
__global__ void __launch_bounds__(128) k_knn_screen() {
    constexpr int NB  = (STAGE == 0) ? NCTX : NALL;
    constexpr int NCL = NB / 12;
    __shared__ int scnt;
    __shared__ int slist[CAP];
    int a = blockIdx.x, b = blockIdx.y;
    int cg = b * NCL + a;
    if (threadIdx.x == 0) scnt = 0;
    __syncthreads();
    float cx = g_ccen[cg * 3 + 0], cy = g_ccen[cg * 3 + 1], cz = g_ccen[cg * 3 + 2];
    float thr = g_crad[cg] + g_crq[cg] + 1e-4f;
    for (int c = threadIdx.x; c < NCL; c += 128) {
        if (c == a) continue;
        int og = b * NCL + c;
        float dx = cx - g_ccen[og * 3 + 0];
        float dy = cy - g_ccen[og * 3 + 1];
        float dz = cz - g_ccen[og * 3 + 2];
        float d2 = dx * dx + dy * dy + dz * dz;
        float lim = thr + g_crad[og];
        if (d2 < lim * lim) {
            int p = atomicAdd(&scnt, 1);
            if (p < CAP) slist[p] = c;
        }
    }
    __syncthreads();
    int n = scnt;
    if (threadIdx.x == 0) g_ccnt[cg] = (n > CAP) ? -1 : n;
    int nn = (n > CAP) ? 0 : n;
    for (int t = threadIdx.x; t < nn; t += 128)
        g_clist[(size_t)cg * CAP + t] = slist[t];
}

// kC: refine per query over candidate clusters (exact d2, lex keys).
// Scan order irrelevant for the final set (running lex top-8 selection);
// output sorted by key -> deterministic.
template<int STAGE>
__global__ void __launch_bounds__(256) k_knn_refine() {
    constexpr int NB  = (STAGE == 0) ? NCTX : NALL;
    constexpr int NCL = NB / 12;
    const float* xyz = (STAGE == 0) ? g_xyz_ctx : g_xyz_all;
    int idx = blockIdx.x * 256 + threadIdx.x;       // grid covers NB*BB exactly
    int b = idx / NB, i = idx - b * NB;
    int base = b * NB;
    float qx = xyz[(base + i) * 3 + 0];
    float qy = xyz[(base + i) * 3 + 1];
    float qz = xyz[(base + i) * 3 + 2];
    float qw = sq3(qx, qy, qz);
    u64 k[8];
    size_t kb = ((size_t)base + i) * 8;
#pragma unroll
    for (int s = 0; s < 8; ++s) k[s] = g_keys[kb + s];
    int a = i / 12;
    int cg = b * NCL + a;
    int n = g_ccnt[cg];
    int nit = (n < 0) ? NCL : n;                    // fallback: all clusters
    for (int t = 0; t < nit; ++t) {
        int c;
        if (n < 0) { c = t; if (c == a) continue; }
        else         c = g_clist[(size_t)cg * CAP + t];
        int jb = c * 12;
#pragma unroll
        for (int jj = 0; jj < 12; ++jj) {
            int j = jb + jj;
            float px = xyz[(base + j) * 3 + 0];
            float py = xyz[(base + j) * 3 + 1];
            float pz = xyz[(base + j) * 3 + 2];
            float pw = sq3(px, py, pz);
            float d2 = refd2(qx, qy, qz, qw, px, py, pz, pw);
            u64 key = dkey(d2, j);
            KEY_INS(k, key);
        }
    }
#pragma unroll
    for (int s = 0; s < 8; ++s)
        g_idx[(base + i) * KK + s] = base + (int)(k[s] & 0xFFFFFFFFu);
}

// tiny 12-point graphs: one thread per query point (pred branch)
__global__ void k_knn_pred() {
    int i = blockIdx.x * 128 + threadIdx.x;
    if (i >= NP_TOT) return;
    int base = (i / RR) * RR;
    int lr = i - base;
    float qx = g_xyz_p[i * 3 + 0], qy = g_xyz_p[i * 3 + 1], qz = g_xyz_p[i * 3 + 2];
    float qsq = sq3(qx, qy, qz);
    float bd[KK]; int bi[KK];
#pragma unroll
    for (int s = 0; s < KK; ++s) { bd[s] = 3.0e38f; bi[s] = 0; }
    for (int j = 0; j < RR; ++j) {
        if (j == lr) continue;
        int jj = base + j;
        float px = g_xyz_p[jj * 3 + 0], py = g_xyz_p[jj * 3 + 1], pz = g_xyz_p[jj * 3 + 2];
        float psq = sq3(px, py, pz);
        float d2 = refd2(qx, qy, qz, qsq, px, py, pz, psq);
        if (d2 < bd[KK - 1]) {
            int pos = KK - 1;
#pragma unroll
            for (int s = KK - 1; s > 0; --s) {
                if (d2 < bd[s - 1]) { bd[s] = bd[s - 1]; bi[s] = bi[s - 1]; pos = s - 1; }
            }
            bd[pos] = d2; bi[pos] = j;
        }
    }
#pragma unroll
    for (int s = 0; s < KK; ++s)
        g_idx[i * KK + s] = base + bi[s];
}

// ------------------------- per-point a/b projection ------------------------
template<int MODE>   // 0 ctx, 1 pred, 2 global
__global__ void k_ab() {
    constexpr int PTS = 16;
    __shared__ __align__(16) float sx[PTS][132];
    const float* feat = (MODE == 0) ? g_ctx_feat : (MODE == 1) ? g_pred_feat : g_featAll;
    const float* xyz  = (MODE == 0) ? g_xyz_ctx  : (MODE == 1) ? g_xyz_p    : g_xyz_all;
    int i0 = blockIdx.x * PTS;
    for (int e = threadIdx.x; e < PTS * 131; e += 256) {
        int p = e / 131, t = e - p * 131;
        int i = i0 + p;
        int fr = (MODE == 2) ? i : (i / RR);
        sx[p][t] = (t < CC) ? feat[(size_t)fr * CC + t] : xyz[i * 3 + (t - CC)];
    }
    __syncthreads();
    int col = threadIdx.x;                // 0..255
    float bb = g_bab[col];
    u64 acc[PTS];
    float tacc[PTS];
    u64 init = pack2(bb, 0.f);
#pragma unroll
    for (int p = 0; p < PTS; ++p) { acc[p] = init; tacc[p] = 0.f; }
    for (int r = 0; r < 128; r += 4) {
        u64 ww01 = pack2(g_Wab[(r + 0) * 256 + col], g_Wab[(r + 1) * 256 + col]);
        u64 ww23 = pack2(g_Wab[(r + 2) * 256 + col], g_Wab[(r + 3) * 256 + col]);
#pragma unroll
        for (int p = 0; p < PTS; ++p) {
            ulonglong2 v = *(const ulonglong2*)&sx[p][r];
            ffma2(acc[p], v.x, ww01);
            ffma2(acc[p], v.y, ww23);
        }
    }
#pragma unroll
    for (int r = 128; r < 131; ++r) {
        float w = g_Wab[r * 256 + col];
#pragma unroll
        for (int p = 0; p < PTS; ++p) tacc[p] = fmaf(sx[p][r], w, tacc[p]);
    }
#pragma unroll
    for (int p = 0; p < PTS; ++p) {
        float2 u = unpack2(acc[p]);
        float res = u.x + u.y + tacc[p];
        int i = i0 + p;
        if (col < CC) g_a[(size_t)i * CC + col] = res;
        else          g_b[(size_t)i * CC + (col - CC)] = res;
    }
}

// --------------------- EdgeConv layer 2 + max aggregate --------------------
template<int MODE>
__global__ void __launch_bounds__(256) k_edge(const float* __restrict__ We2,
                                              const float* __restrict__ be2) {
    constexpr int PTS = 8;
    __shared__ __align__(16) float shid[128 * 68];    // [h][e], stride 68
    int i0 = blockIdx.x * PTS;
    int c = threadIdx.x & 127, half = threadIdx.x >> 7;
#pragma unroll
    for (int p2 = 0; p2 < 4; ++p2) {
        int p = half * 4 + p2;
        int i = i0 + p;
        float av = g_a[(size_t)i * CC + c];
#pragma unroll
        for (int j = 0; j < KK; ++j) {
            int nb = g_idx[i * KK + j];
            float bv = g_b[(size_t)nb * CC + c];
            shid[c * 68 + p * KK + j] = fmaxf(__fadd_rn(av, bv), 0.f);
        }
    }
    __syncthreads();
    u64 acc[16];
#pragma unroll
    for (int e = 0; e < 16; ++e) acc[e] = 0ull;
    const float* wp_ = We2 + c;
#pragma unroll 2
    for (int h = 0; h < 128; ++h) {
        float w = wp_[h * CC];
        u64 ww = pack2(w, w);
        const ulonglong2* hp = (const ulonglong2*)&shid[h * 68 + half * 32];
#pragma unroll
        for (int e = 0; e < 8; ++e) {
            ulonglong2 v = hp[e];
            ffma2(acc[2 * e + 0], v.x, ww);
            ffma2(acc[2 * e + 1], v.y, ww);
        }
    }
    float bb = be2[c];
#pragma unroll
    for (int p2 = 0; p2 < 4; ++p2) {
        float2 v0 = unpack2(acc[p2 * 4 + 0]);
        float2 v1 = unpack2(acc[p2 * 4 + 1]);
        float2 v2 = unpack2(acc[p2 * 4 + 2]);
        float2 v3 = unpack2(acc[p2 * 4 + 3]);
        float mx = fmaxf(fmaxf(fmaxf(v0.x, v0.y), fmaxf(v1.x, v1.y)),
                         fmaxf(fmaxf(v2.x, v2.y), fmaxf(v3.x, v3.y)));
        g_featAll[(size_t)mapOut<MODE>(i0 + half * 4 + p2) * CC + c] = mx + bb;
    }
}

// ------------------------------ offset MLP ---------------------------------
template<int MODE>
__global__ void __launch_bounds__(128) k_offset(const float* __restrict__ W1,
                                                const float* __restrict__ b1,
                                                const float* __restrict__ W2,
                                                const float* __restrict__ b2,
                                                float* __restrict__ outp) {
    constexpr int PTS = 8;
    __shared__ __align__(16) float sf[PTS][CC];
    __shared__ float sh[PTS][CC];
    int i0 = blockIdx.x * PTS, tid = threadIdx.x;
#pragma unroll
    for (int p = 0; p < PTS; ++p)
        sf[p][tid] = g_featAll[(size_t)mapOut<MODE>(i0 + p) * CC + tid];
    __syncthreads();
    float bb = b1[tid];
    u64 acc[PTS];
    u64 init = pack2(bb, 0.f);
#pragma unroll
    for (int p = 0; p < PTS; ++p) acc[p] = init;
    for (int r = 0; r < CC; r += 2) {
        u64 ww = pack2(W1[(r + 0) * CC + tid], W1[(r + 1) * CC + tid]);
#pragma unroll
        for (int p = 0; p < PTS; ++p) {
            u64 v = *(const u64*)&sf[p][r];
            ffma2(acc[p], v, ww);
        }
    }
#pragma unroll
    for (int p = 0; p < PTS; ++p) {
        float2 u = unpack2(acc[p]);
        sh[p][tid] = fmaxf(u.x + u.y, 0.f);
    }
    __syncthreads();
    int wp0 = (tid >> 5) * 2, l = tid & 31;
#pragma unroll
    for (int t = 0; t < 2; ++t) {
        int wp = wp0 + t;
        int i = i0 + wp;
        float s0 = 0.f, s1 = 0.f, s2 = 0.f;
        for (int h = l; h < CC; h += 32) {
            float hv = sh[wp][h];
            s0 = fmaf(hv, W2[h * 3 + 0], s0);
            s1 = fmaf(hv, W2[h * 3 + 1], s1);
            s2 = fmaf(hv, W2[h * 3 + 2], s2);
        }
#pragma unroll
        for (int off = 16; off; off >>= 1) {
            s0 += __shfl_down_sync(0xffffffffu, s0, off);
            s1 += __shfl_down_sync(0xffffffffu, s1, off);
            s2 += __shfl_down_sync(0xffffffffu, s2, off);
        }
        if (l == 0) {
            const float* xin = (MODE == 0) ? g_xyz_ctx : (MODE == 1) ? g_xyz_p : g_xyz_all;
            float* orow;
            if (MODE == 2) orow = outp + (size_t)i * 3;
            else           orow = g_xyz_all + (size_t)mapOut<MODE>(i) * 3;
            orow[0] = xin[i * 3 + 0] + s0 + b2[0];
            orow[1] = xin[i * 3 + 1] + s1 + b2[1];
            orow[2] = xin[i * 3 + 2] + s2 + b2[2];
        }
    }
}

// ------------------------------- launcher ----------------------------------
extern "C" void kernel_launch(void* const* d_in, const int* in_sizes, int n_in,
                              void* d_out, int out_size) {
    const float* ctx_xyz     = (const float*)d_in[0];
    const float* ctx_tokens  = (const float*)d_in[1];
    const float* pred_tokens = (const float*)d_in[2];
    const float* noise_ctx   = (const float*)d_in[3];
    const float* noise_pred  = (const float*)d_in[4];
    const float* Wp  = (const float*)d_in[5];
    const float* bp  = (const float*)d_in[6];
    const float* We1 = (const float*)d_in[7];
    const float* be1 = (const float*)d_in[8];
    const float* We2 = (const float*)d_in[9];
    const float* be2 = (const float*)d_in[10];
    const float* Wc1 = (const float*)d_in[11];
    const float* bc1 = (const float*)d_in[12];
    const float* Wc2 = (const float*)d_in[13];
    const float* bc2 = (const float*)d_in[14];
    const float* Wq1 = (const float*)d_in[15];
    const float* bq1 = (const float*)d_in[16];
    const float* Wq2 = (const float*)d_in[17];
    const float* bq2 = (const float*)d_in[18];
    const float* Wf1 = (const float*)d_in[19];
    const float* bf1 = (const float*)d_in[20];
    const float* Wf2 = (const float*)d_in[21];
    const float* bf2 = (const float*)d_in[22];
    (void)in_sizes; (void)n_in; (void)out_size;
    float* out = (float*)d_out;

    // launch 4 == ncu-captured slot -> k_knn_refine<0> this round
    k_xyz_ctx<<<NC_TOT / 128, 128>>>(ctx_xyz, noise_ctx);              // 1
    k_knn_own<0><<<dim3(NCTX / 192, BB), 192>>>();                     // 2
    k_knn_screen<0><<<dim3(NCTX / 12, BB), 128>>>();                   // 3
    k_knn_refine<0><<<NC_TOT / 256, 256>>>();                          // 4 (profiled)
    k_wab<<<(131 * 128 + 255) / 256, 256>>>(We1, be1);
    k_proj<0><<<BB * PP / 8, 128>>>(ctx_tokens, Wp, bp);
    k_anchor<<<BB, 128>>>(ctx_xyz);
    k_xyz_pred<<<NP_TOT / 128, 128>>>(noise_pred);
    k_proj<1><<<BB * MMH / 8, 128>>>(pred_tokens, Wp, bp);

    // ---- context branch ----
    k_ab<0><<<NC_TOT / 16, 256>>>();
    k_edge<0><<<NC_TOT / 8, 256>>>(We2, be2);
    k_offset<0><<<NC_TOT / 8, 128>>>(Wc1, bc1, Wc2, bc2, nullptr);

    // ---- prediction branch ----
    k_knn_pred<<<NP_TOT / 128, 128>>>();
    k_ab<1><<<NP_TOT / 16, 256>>>();
    k_edge<1><<<NP_TOT / 8, 256>>>(We2, be2);
    k_offset<1><<<NP_TOT / 8, 128>>>(Wq1, bq1, Wq2, bq2, nullptr);

    // ---- global refinement ----
    k_knn_own<2><<<dim3(NALL / 192, BB), 192>>>();
    k_knn_screen<2><<<dim3(NALL / 12, BB), 128>>>();
    k_knn_refine<2><<<NA_TOT / 256, 256>>>();
    k_ab<2><<<NA_TOT / 16, 256>>>();
    k_edge<2><<<NA_TOT / 8, 256>>>(We2, be2);
    k_offset<2><<<NA_TOT / 8, 128>>>(Wf1, bf1, Wf2, bf2, out);
}

// round 16
// speedup vs baseline: 1.3977x; 1.0925x over previous
#include <cuda_runtime.h>

// ---------------------------------------------------------------------------
// JEPAPointDecoder — full pipeline on GB300, fp32 with packed f32x2 FMA.
// (Resubmit of R14: prior round died to a broker/container infra failure
//  before any compile or run feedback; kernel itself is unmeasured.)
//
// Shapes: B=4, P=384, M=64, TOK=1024, C=128, R=12, k=8
//
// EdgeConv layer-1 factorization:  msg@We1 = a_i + b_j  with
//   a_i = x_i @ (We1_top - We1_bot) + be1,   b_j = x_j @ We1_bot
//
// kNN: exact cluster-screened (12-replica clusters; own-cluster bound +
// triangle-inequality screen with conservative fp margins; refinement with
// bit-identical reference d2 and lex (ordered-d2, idx) keys).
//
// k_edge density rewrite — 128 thr = 64 col-pairs x 2 edge-halves,
// 2 cols x 32 edges per thread (1 LDG.64 weight + 8 LDS.128 per 32 FFMA2);
// k_ab weights transposed (LDG.128 per 4 rows). Bitwise-identical outputs.
// ---------------------------------------------------------------------------

#define BB     4
#define PP     384
#define MMH    64
#define TOKN   1024
#define CC     128
#define RR     12
#define KK     8
#define NCTX   (PP*RR)        // 4608
#define NPRED  (MMH*RR)       // 768
#define NALL   (NCTX+NPRED)   // 5376
#define NC_TOT (BB*NCTX)      // 18432
#define NP_TOT (BB*NPRED)     // 3072
#define NA_TOT (BB*NALL)      // 21504
#define NCLMAX (NALL/12)      // 448 clusters per batch (global stage)
#define CAP    120            // cluster-list capacity (overflow -> fallback)

// ----------------------------- scratch ------------------------------------
__device__ float g_anchor[BB*3];
__device__ float g_ctx_feat[BB*PP*CC];
__device__ float g_pred_feat[BB*MMH*CC];
__device__ float g_xyz_ctx[NC_TOT*3];
__device__ float g_xyz_p[NP_TOT*3];
__device__ float g_xyz_all[NA_TOT*3];
__device__ float g_featAll[(size_t)NA_TOT*CC];
__device__ float g_a[(size_t)NA_TOT*CC];
__device__ float g_b[(size_t)NA_TOT*CC];
__device__ int   g_idx[NA_TOT*KK];
__device__ float g_WabT[256*132];     // transposed: [col][r], r-pad 132
__device__ float g_bab[256];

typedef unsigned long long u64;
__device__ u64   g_keys[(size_t)NA_TOT*8];      // per-query top-8 lex keys
__device__ float g_ccen[BB*NCLMAX*3];
__device__ float g_crad[BB*NCLMAX];
__device__ float g_crq[BB*NCLMAX];
__device__ int   g_ccnt[BB*NCLMAX];
__device__ int   g_clist[BB*NCLMAX*CAP];

// --------------------------- f32x2 primitives ------------------------------
__device__ __forceinline__ void ffma2(u64& d, u64 a, u64 b) {
    asm("fma.rn.f32x2 %0, %1, %2, %0;" : "+l"(d) : "l"(a), "l"(b));
}
__device__ __forceinline__ u64 pack2(float lo, float hi) {
    u64 r;
    unsigned int a = __float_as_uint(lo), b = __float_as_uint(hi);
    asm("mov.b64 %0, {%1, %2};" : "=l"(r) : "r"(a), "r"(b));
    return r;
}
__device__ __forceinline__ float2 unpack2(u64 v) {
    unsigned int a, b;
    asm("mov.b64 {%0, %1}, %2;" : "=r"(a), "=r"(b) : "l"(v));
    return make_float2(__uint_as_float(a), __uint_as_float(b));
}

// ----------------------------- helpers ------------------------------------
template<int MODE>
__device__ __forceinline__ int mapOut(int i) {
    if (MODE == 0) return (i / NCTX)  * NALL + (i % NCTX);           // ctx
    if (MODE == 1) return (i / NPRED) * NALL + NCTX + (i % NPRED);   // pred
    return i;                                                        // global
}

__device__ __forceinline__ float sq3(float x, float y, float z) {
    return __fadd_rn(__fadd_rn(__fmul_rn(x, x), __fmul_rn(y, y)), __fmul_rn(z, z));
}

// order-preserving float->uint (monotone; -0 cannot occur for our d2)
__device__ __forceinline__ unsigned int ordf(float f) {
    unsigned int b = __float_as_uint(f);
    return (b & 0x80000000u) ? ~b : (b | 0x80000000u);
}
__device__ __forceinline__ float iordf(unsigned int h) {
    unsigned int b = (h & 0x80000000u) ? (h & 0x7FFFFFFFu) : ~h;
    return __uint_as_float(b);
}
__device__ __forceinline__ u64 dkey(float d2, int j) {
    return ((u64)ordf(d2) << 32) | (unsigned int)j;
}
// exact reference d2: sub(add(qw,pw), mul(2,dot)), dot = mul,fma,fma
__device__ __forceinline__ float refd2(float qx, float qy, float qz, float qw,
                                       float px, float py, float pz, float pw) {
    float dot = __fmul_rn(qx, px);
    dot = __fmaf_rn(qy, py, dot);
    dot = __fmaf_rn(qz, pz, dot);
    return __fsub_rn(__fadd_rn(qw, pw), __fmul_rn(2.0f, dot));
}
// sorted strict-< insert of key into ascending k[0..7]
#define KEY_INS(k, key) do {                                            \
    if ((key) < k[7]) {                                                 \
        int _pos = 7;                                                   \
        _Pragma("unroll")                                               \
        for (int _s = 7; _s > 0; --_s)                                  \
            if ((key) < k[_s - 1]) { k[_s] = k[_s - 1]; _pos = _s - 1; }\
        k[_pos] = (key);                                                \
    } } while (0)

// ----------------------------- anchors ------------------------------------
__global__ void k_anchor(const float* __restrict__ ctx_xyz) {
    int b = blockIdx.x, tid = threadIdx.x;
    __shared__ float sred[3][128];
    float sx = 0.f, sy = 0.f, sz = 0.f;
    for (int p = tid; p < PP; p += 128) {
        const float* q = &ctx_xyz[(b * PP + p) * 3];
        sx += q[0]; sy += q[1]; sz += q[2];
    }
    sred[0][tid] = sx; sred[1][tid] = sy; sred[2][tid] = sz;
    __syncthreads();
    for (int s = 64; s > 0; s >>= 1) {
        if (tid < s) {
            sred[0][tid] += sred[0][tid + s];
            sred[1][tid] += sred[1][tid + s];
            sred[2][tid] += sred[2][tid + s];
        }
        __syncthreads();
    }
    if (tid == 0) {
        g_anchor[b * 3 + 0] = __fdiv_rn(sred[0][0], (float)PP);
        g_anchor[b * 3 + 1] = __fdiv_rn(sred[1][0], (float)PP);
        g_anchor[b * 3 + 2] = __fdiv_rn(sred[2][0], (float)PP);
    }
}

// --------------------------- token projection -----------------------------
template<int WHICH>
__global__ void k_proj(const float* __restrict__ tokens,
                       const float* __restrict__ Wp,
                       const float* __restrict__ bp) {
    constexpr int RPB = 8;
    __shared__ __align__(16) float st[RPB * TOKN];        // 32 KB
    float* out = (WHICH == 0) ? g_ctx_feat : g_pred_feat;
    int r0 = blockIdx.x * RPB;
    for (int e = threadIdx.x; e < RPB * TOKN; e += 128)
        st[e] = tokens[(size_t)r0 * TOKN + e];
    __syncthreads();
    int c = threadIdx.x;
    float bb = bp[c];
    u64 acc[RPB];
#pragma unroll
    for (int r = 0; r < RPB; ++r) acc[r] = pack2(bb, 0.f);
    for (int t = 0; t < TOKN; t += 4) {
        float w0 = Wp[(t + 0) * CC + c];
        float w1 = Wp[(t + 1) * CC + c];
        float w2 = Wp[(t + 2) * CC + c];
        float w3 = Wp[(t + 3) * CC + c];
        u64 ww01 = pack2(w0, w1);
        u64 ww23 = pack2(w2, w3);
#pragma unroll
        for (int r = 0; r < RPB; ++r) {
            ulonglong2 v = *(const ulonglong2*)&st[r * TOKN + t];
            ffma2(acc[r], v.x, ww01);
            ffma2(acc[r], v.y, ww23);
        }
    }
#pragma unroll
    for (int r = 0; r < RPB; ++r) {
        float2 u = unpack2(acc[r]);
        out[(size_t)(r0 + r) * CC + c] = u.x + u.y;
    }
}

// --------------------------- Wab construction (transposed) -----------------
__global__ void k_wab(const float* __restrict__ We1, const float* __restrict__ be1) {
    int t = blockIdx.x * 256 + threadIdx.x;
    if (t < 131 * 128) {
        int r = t >> 7, c = t & 127;
        float top = We1[r * CC + c];
        float bot = We1[(131 + r) * CC + c];
        g_WabT[c * 132 + r]         = __fsub_rn(top, bot);
        g_WabT[(128 + c) * 132 + r] = bot;
    }
    if (t < 128) { g_bab[t] = be1[t]; g_bab[128 + t] = 0.f; }
}

// ------------------------------ xyz builders ------------------------------
__global__ void k_xyz_ctx(const float* __restrict__ ctx_xyz,
                          const float* __restrict__ noise) {
    int i = blockIdx.x * 128 + threadIdx.x;
    if (i >= NC_TOT) return;
    float nx = noise[i * 3 + 0], ny = noise[i * 3 + 1], nz = noise[i * 3 + 2];
    float denom = __fadd_rn(sqrtf(sq3(nx, ny, nz)), 1e-6f);
    int bp = i / RR;
    g_xyz_ctx[i * 3 + 0] = __fadd_rn(ctx_xyz[bp * 3 + 0], __fmul_rn(__fdiv_rn(nx, denom), 0.02f));
    g_xyz_ctx[i * 3 + 1] = __fadd_rn(ctx_xyz[bp * 3 + 1], __fmul_rn(__fdiv_rn(ny, denom), 0.02f));
    g_xyz_ctx[i * 3 + 2] = __fadd_rn(ctx_xyz[bp * 3 + 2], __fmul_rn(__fdiv_rn(nz, denom), 0.02f));
}

__global__ void k_xyz_pred(const float* __restrict__ noise) {
    int i = blockIdx.x * 128 + threadIdx.x;
    if (i >= NP_TOT) return;
    float nx = noise[i * 3 + 0], ny = noise[i * 3 + 1], nz = noise[i * 3 + 2];
    float denom = __fadd_rn(sqrtf(sq3(nx, ny, nz)), 1e-6f);
    int b = i / NPRED;
    g_xyz_p[i * 3 + 0] = __fadd_rn(g_anchor[b * 3 + 0], __fmul_rn(__fdiv_rn(nx, denom), 0.05f));
    g_xyz_p[i * 3 + 1] = __fadd_rn(g_anchor[b * 3 + 1], __fmul_rn(__fdiv_rn(ny, denom), 0.05f));
    g_xyz_p[i * 3 + 2] = __fadd_rn(g_anchor[b * 3 + 2], __fmul_rn(__fdiv_rn(nz, denom), 0.05f));
}

// ===================== cluster-screened exact kNN ==========================
// kA: own-cluster top-8 + cluster center/radius/query-bound
template<int STAGE>  // 0: ctx, 2: global
__global__ void __launch_bounds__(192) k_knn_own() {
    constexpr int NB  = (STAGE == 0) ? NCTX : NALL;
    constexpr int NCL = NB / 12;
    const float* xyz = (STAGE == 0) ? g_xyz_ctx : g_xyz_all;
    __shared__ float4 spt[192];
    __shared__ float sbd[192];
    int b = blockIdx.y, tid = threadIdx.x;
    int i0 = blockIdx.x * 192;
    int i = i0 + tid;                 // batch-local query
    int base = b * NB;
    {
        float x = xyz[(base + i) * 3 + 0];
        float y = xyz[(base + i) * 3 + 1];
        float z = xyz[(base + i) * 3 + 2];
        spt[tid] = make_float4(x, y, z, sq3(x, y, z));
    }
    __syncthreads();
    int lc = tid / 12, r = tid - lc * 12;
    int lbase = lc * 12;
    float4 pq = spt[tid];
    u64 k[8];
#pragma unroll
    for (int s = 0; s < 8; ++s) k[s] = 0xFFFFFFFFFFFFFFFFull;
#pragma unroll
    for (int jj = 0; jj < 12; ++jj) {
        if (jj == r) continue;
        float4 pj = spt[lbase + jj];
        float d2 = refd2(pq.x, pq.y, pq.z, pq.w, pj.x, pj.y, pj.z, pj.w);
        u64 key = dkey(d2, i0 + lbase + jj);
        KEY_INS(k, key);
    }
    size_t kb = ((size_t)base + i) * 8;
#pragma unroll
    for (int s = 0; s < 8; ++s) g_keys[kb + s] = k[s];
    sbd[tid] = iordf((unsigned int)(k[7] >> 32));   // bd7 (11 cands >= 8: filled)
    __syncthreads();
    if (r == 0) {
        float mb = 0.f, sx = 0.f, sy = 0.f, sz = 0.f;
        for (int t = 0; t < 12; ++t) {
            mb = fmaxf(mb, sbd[lbase + t]);
            float4 p = spt[lbase + t];
            sx += p.x; sy += p.y; sz += p.z;
        }
        float cx = sx / 12.f, cy = sy / 12.f, cz = sz / 12.f;
        float mr2 = 0.f;
        for (int t = 0; t < 12; ++t) {
            float4 p = spt[lbase + t];
            float dx = p.x - cx, dy = p.y - cy, dz = p.z - cz;
            mr2 = fmaxf(mr2, dx * dx + dy * dy + dz * dz);
        }
        int cg = b * NCL + i / 12;
        g_ccen[cg * 3 + 0] = cx; g_ccen[cg * 3 + 1] = cy; g_ccen[cg * 3 + 2] = cz;
        g_crad[cg] = sqrtf(mr2) * 1.0001f + 1e-5f;
        g_crq[cg]  = sqrtf(fmaxf(mb, 0.f)) * 1.0001f + 1e-5f;
    }
}

// kB: conservative cluster-pair screen -> per-cluster candidate list
template<int STAGE>
__global__ void __launch_bounds__(128) k_knn_screen() {
    constexpr int NB  = (STAGE == 0) ? NCTX : NALL;
    constexpr int NCL = NB / 12;
    __shared__ int scnt;
    __shared__ int slist[CAP];
    int a = blockIdx.x, b = blockIdx.y;
    int cg = b * NCL + a;
    if (threadIdx.x == 0) scnt = 0;
    __syncthreads();
    float cx = g_ccen[cg * 3 + 0], cy = g_ccen[cg * 3 + 1], cz = g_ccen[cg * 3 + 2];
    float thr = g_crad[cg] + g_crq[cg] + 1e-4f;
    for (int c = threadIdx.x; c < NCL; c += 128) {
        if (c == a) continue;
        int og = b * NCL + c;
        float dx = cx - g_ccen[og * 3 + 0];
        float dy = cy - g_ccen[og * 3 + 1];
        float dz = cz - g_ccen[og * 3 + 2];
        float d2 = dx * dx + dy * dy + dz * dz;
        float lim = thr + g_crad[og];
        if (d2 < lim * lim) {
            int p = atomicAdd(&scnt, 1);
            if (p < CAP) slist[p] = c;
        }
    }
    __syncthreads();
    int n = scnt;
    if (threadIdx.x == 0) g_ccnt[cg] = (n > CAP) ? -1 : n;
    int nn = (n > CAP) ? 0 : n;
    for (int t = threadIdx.x; t < nn; t += 128)
        g_clist[(size_t)cg * CAP + t] = slist[t];
}

// kC: refine per query over candidate clusters (exact d2, lex keys).
template<int STAGE>
__global__ void __launch_bounds__(256) k_knn_refine() {
    constexpr int NB  = (STAGE == 0) ? NCTX : NALL;
    constexpr int NCL = NB / 12;
    const float* xyz = (STAGE == 0) ? g_xyz_ctx : g_xyz_all;
    int idx = blockIdx.x * 256 + threadIdx.x;       // grid covers NB*BB exactly
    int b = idx / NB, i = idx - b * NB;
    int base = b * NB;
    float qx = xyz[(base + i) * 3 + 0];
    float qy = xyz[(base + i) * 3 + 1];
    float qz = xyz[(base + i) * 3 + 2];
    float qw = sq3(qx, qy, qz);
    u64 k[8];
    size_t kb = ((size_t)base + i) * 8;
#pragma unroll
    for (int s = 0; s < 8; ++s) k[s] = g_keys[kb + s];
    int a = i / 12;
    int cg = b * NCL + a;
    int n = g_ccnt[cg];
    int nit = (n < 0) ? NCL : n;                    // fallback: all clusters
    for (int t = 0; t < nit; ++t) {
        int c;
        if (n < 0) { c = t; if (c == a) continue; }
        else         c = g_clist[(size_t)cg * CAP + t];
        int jb = c * 12;
#pragma unroll
        for (int jj = 0; jj < 12; ++jj) {
            int j = jb + jj;
            float px = xyz[(base + j) * 3 + 0];
            float py = xyz[(base + j) * 3 + 1];
            float pz = xyz[(base + j) * 3 + 2];
            float pw = sq3(px, py, pz);
            float d2 = refd2(qx, qy, qz, qw, px, py, pz, pw);
            u64 key = dkey(d2, j);
            KEY_INS(k, key);
        }
    }
#pragma unroll
    for (int s = 0; s < 8; ++s)
        g_idx[(base + i) * KK + s] = base + (int)(k[s] & 0xFFFFFFFFu);
}

// tiny 12-point graphs: one thread per query point (pred branch)
__global__ void k_knn_pred() {
    int i = blockIdx.x * 128 + threadIdx.x;
    if (i >= NP_TOT) return;
    int base = (i / RR) * RR;
    int lr = i - base;
    float qx = g_xyz_p[i * 3 + 0], qy = g_xyz_p[i * 3 + 1], qz = g_xyz_p[i * 3 + 2];
    float qsq = sq3(qx, qy, qz);
    float bd[KK]; int bi[KK];
#pragma unroll
    for (int s = 0; s < KK; ++s) { bd[s] = 3.0e38f; bi[s] = 0; }
    for (int j = 0; j < RR; ++j) {
        if (j == lr) continue;
        int jj = base + j;
        float px = g_xyz_p[jj * 3 + 0], py = g_xyz_p[jj * 3 + 1], pz = g_xyz_p[jj * 3 + 2];
        float psq = sq3(px, py, pz);
        float d2 = refd2(qx, qy, qz, qsq, px, py, pz, psq);
        if (d2 < bd[KK - 1]) {
            int pos = KK - 1;
#pragma unroll
            for (int s = KK - 1; s > 0; --s) {
                if (d2 < bd[s - 1]) { bd[s] = bd[s - 1]; bi[s] = bi[s - 1]; pos = s - 1; }
            }
            bd[pos] = d2; bi[pos] = j;
        }
    }
#pragma unroll
    for (int s = 0; s < KK; ++s)
        g_idx[i * KK + s] = base + bi[s];
}

// ------------------------- per-point a/b projection ------------------------
template<int MODE>   // 0 ctx, 1 pred, 2 global
__global__ void k_ab() {
    constexpr int PTS = 16;
    __shared__ __align__(16) float sx[PTS][132];
    const float* feat = (MODE == 0) ? g_ctx_feat : (MODE == 1) ? g_pred_feat : g_featAll;
    const float* xyz  = (MODE == 0) ? g_xyz_ctx  : (MODE == 1) ? g_xyz_p    : g_xyz_all;
    int i0 = blockIdx.x * PTS;
    for (int e = threadIdx.x; e < PTS * 131; e += 256) {
        int p = e / 131, t = e - p * 131;
        int i = i0 + p;
        int fr = (MODE == 2) ? i : (i / RR);
        sx[p][t] = (t < CC) ? feat[(size_t)fr * CC + t] : xyz[i * 3 + (t - CC)];
    }
    __syncthreads();
    int col = threadIdx.x;                // 0..255
    float bb = g_bab[col];
    u64 acc[PTS];
    float tacc[PTS];
    u64 init = pack2(bb, 0.f);
#pragma unroll
    for (int p = 0; p < PTS; ++p) { acc[p] = init; tacc[p] = 0.f; }
    const float* wt = &g_WabT[col * 132];
    for (int r = 0; r < 128; r += 4) {
        float4 wv = *(const float4*)&wt[r];
        u64 ww01 = pack2(wv.x, wv.y);
        u64 ww23 = pack2(wv.z, wv.w);
#pragma unroll
        for (int p = 0; p < PTS; ++p) {
            ulonglong2 v = *(const ulonglong2*)&sx[p][r];
            ffma2(acc[p], v.x, ww01);
            ffma2(acc[p], v.y, ww23);
        }
    }
#pragma unroll
    for (int r = 128; r < 131; ++r) {
        float w = wt[r];
#pragma unroll
        for (int p = 0; p < PTS; ++p) tacc[p] = fmaf(sx[p][r], w, tacc[p]);
    }
#pragma unroll
    for (int p = 0; p < PTS; ++p) {
        float2 u = unpack2(acc[p]);
        float res = u.x + u.y + tacc[p];
        int i = i0 + p;
        if (col < CC) g_a[(size_t)i * CC + col] = res;
        else          g_b[(size_t)i * CC + (col - CC)] = res;
    }
}

// --------------------- EdgeConv layer 2 + max aggregate --------------------
// out[i,c] = max_j ( relu(a_i + b_{n_j}) @ We2[:,c] ) + be2[c]
// 128 threads = 64 col-pairs x 2 edge-halves; each thread: 2 adjacent cols
// x 32 edges (acc 32 u64). Per h: 8 LDS.128 (broadcast) + 1 LDG.64 weights
// + 32 FFMA2. Per-edge h-order identical to before -> bitwise same output.
template<int MODE>
__global__ void __launch_bounds__(128) k_edge(const float* __restrict__ We2,
                                              const float* __restrict__ be2) {
    constexpr int PTS = 8;                            // 64 edges / block
    __shared__ __align__(16) float shid[128 * 68];    // [h][e], stride 68
    int i0 = blockIdx.x * PTS;
    int tid = threadIdx.x;
    {   // build: thread owns h-row tid
        int h = tid;
#pragma unroll
        for (int p = 0; p < PTS; ++p) {
            int i = i0 + p;
            float av = g_a[(size_t)i * CC + h];
#pragma unroll
            for (int j = 0; j < KK; ++j) {
                int nb = g_idx[i * KK + j];
                float bv = g_b[(size_t)nb * CC + h];
                shid[h * 68 + p * KK + j] = fmaxf(__fadd_rn(av, bv), 0.f);
            }
        }
    }
    __syncthreads();
    int cs = tid & 63, eh = tid >> 6;    // col-slot (2 cols), edge-half (32 edges)
    int c0 = cs * 2;
    u64 acc[32];
#pragma unroll
    for (int e = 0; e < 32; ++e) acc[e] = 0ull;
#pragma unroll 2
    for (int h = 0; h < 128; ++h) {
        float2 wv = *(const float2*)&We2[h * CC + c0];
        u64 w0 = pack2(wv.x, wv.x);
        u64 w1 = pack2(wv.y, wv.y);
        const ulonglong2* hp = (const ulonglong2*)&shid[h * 68 + eh * 32];
#pragma unroll
        for (int e2 = 0; e2 < 8; ++e2) {
            ulonglong2 v = hp[e2];
            ffma2(acc[e2 * 2 + 0],      v.x, w0);
            ffma2(acc[e2 * 2 + 1],      v.y, w0);
            ffma2(acc[16 + e2 * 2 + 0], v.x, w1);
            ffma2(acc[16 + e2 * 2 + 1], v.y, w1);
        }
    }
    float2 bb = *(const float2*)&be2[c0];
#pragma unroll
    for (int p2 = 0; p2 < 4; ++p2) {                  // points eh*4 + p2
        float2 a0 = unpack2(acc[p2 * 4 + 0]);
        float2 a1 = unpack2(acc[p2 * 4 + 1]);
        float2 a2 = unpack2(acc[p2 * 4 + 2]);
        float2 a3 = unpack2(acc[p2 * 4 + 3]);
        float mx0 = fmaxf(fmaxf(fmaxf(a0.x, a0.y), fmaxf(a1.x, a1.y)),
                          fmaxf(fmaxf(a2.x, a2.y), fmaxf(a3.x, a3.y)));
        float2 b0 = unpack2(acc[16 + p2 * 4 + 0]);
        float2 b1 = unpack2(acc[16 + p2 * 4 + 1]);
        float2 b2 = unpack2(acc[16 + p2 * 4 + 2]);
        float2 b3 = unpack2(acc[16 + p2 * 4 + 3]);
        float mx1 = fmaxf(fmaxf(fmaxf(b0.x, b0.y), fmaxf(b1.x, b1.y)),
                          fmaxf(fmaxf(b2.x, b2.y), fmaxf(b3.x, b3.y)));
        int row = mapOut<MODE>(i0 + eh * 4 + p2);
        *(float2*)&g_featAll[(size_t)row * CC + c0] =
            make_float2(mx0 + bb.x, mx1 + bb.y);
    }
}

// ------------------------------ offset MLP ---------------------------------
template<int MODE>
__global__ void __launch_bounds__(128) k_offset(const float* __restrict__ W1,
                                                const float* __restrict__ b1,
                                                const float* __restrict__ W2,
                                                const float* __restrict__ b2,
                                                float* __restrict__ outp) {
    constexpr int PTS = 8;
    __shared__ __align__(16) float sf[PTS][CC];
    __shared__ float sh[PTS][CC];
    int i0 = blockIdx.x * PTS, tid = threadIdx.x;
#pragma unroll
    for (int p = 0; p < PTS; ++p)
        sf[p][tid] = g_featAll[(size_t)mapOut<MODE>(i0 + p) * CC + tid];
    __syncthreads();
    float bb = b1[tid];
    u64 acc[PTS];
    u64 init = pack2(bb, 0.f);
#pragma unroll
    for (int p = 0; p < PTS; ++p) acc[p] = init;
    for (int r = 0; r < CC; r += 2) {
        u64 ww = pack2(W1[(r + 0) * CC + tid], W1[(r + 1) * CC + tid]);
#pragma unroll
        for (int p = 0; p < PTS; ++p) {
            u64 v = *(const u64*)&sf[p][r];
            ffma2(acc[p], v, ww);
        }
    }
#pragma unroll
    for (int p = 0; p < PTS; ++p) {
        float2 u = unpack2(acc[p]);
        sh[p][tid] = fmaxf(u.x + u.y, 0.f);
    }
    __syncthreads();
    int wp0 = (tid >> 5) * 2, l = tid & 31;
#pragma unroll
    for (int t = 0; t < 2; ++t) {
        int wp = wp0 + t;
        int i = i0 + wp;
        float s0 = 0.f, s1 = 0.f, s2 = 0.f;
        for (int h = l; h < CC; h += 32) {
            float hv = sh[wp][h];
            s0 = fmaf(hv, W2[h * 3 + 0], s0);
            s1 = fmaf(hv, W2[h * 3 + 1], s1);
            s2 = fmaf(hv, W2[h * 3 + 2], s2);
        }
#pragma unroll
        for (int off = 16; off; off >>= 1) {
            s0 += __shfl_down_sync(0xffffffffu, s0, off);
            s1 += __shfl_down_sync(0xffffffffu, s1, off);
            s2 += __shfl_down_sync(0xffffffffu, s2, off);
        }
        if (l == 0) {
            const float* xin = (MODE == 0) ? g_xyz_ctx : (MODE == 1) ? g_xyz_p : g_xyz_all;
            float* orow;
            if (MODE == 2) orow = outp + (size_t)i * 3;
            else           orow = g_xyz_all + (size_t)mapOut<MODE>(i) * 3;
            orow[0] = xin[i * 3 + 0] + s0 + b2[0];
            orow[1] = xin[i * 3 + 1] + s1 + b2[1];
            orow[2] = xin[i * 3 + 2] + s2 + b2[2];
        }
    }
}

// ------------------------------- launcher ----------------------------------
extern "C" void kernel_launch(void* const* d_in, const int* in_sizes, int n_in,
                              void* d_out, int out_size) {
    const float* ctx_xyz     = (const float*)d_in[0];
    const float* ctx_tokens  = (const float*)d_in[1];
    const float* pred_tokens = (const float*)d_in[2];
    const float* noise_ctx   = (const float*)d_in[3];
    const float* noise_pred  = (const float*)d_in[4];
    const float* Wp  = (const float*)d_in[5];
    const float* bp  = (const float*)d_in[6];
    const float* We1 = (const float*)d_in[7];
    const float* be1 = (const float*)d_in[8];
    const float* We2 = (const float*)d_in[9];
    const float* be2 = (const float*)d_in[10];
    const float* Wc1 = (const float*)d_in[11];
    const float* bc1 = (const float*)d_in[12];
    const float* Wc2 = (const float*)d_in[13];
    const float* bc2 = (const float*)d_in[14];
    const float* Wq1 = (const float*)d_in[15];
    const float* bq1 = (const float*)d_in[16];
    const float* Wq2 = (const float*)d_in[17];
    const float* bq2 = (const float*)d_in[18];
    const float* Wf1 = (const float*)d_in[19];
    const float* bf1 = (const float*)d_in[20];
    const float* Wf2 = (const float*)d_in[21];
    const float* bf2 = (const float*)d_in[22];
    (void)in_sizes; (void)n_in; (void)out_size;
    float* out = (float*)d_out;

    k_xyz_ctx<<<NC_TOT / 128, 128>>>(ctx_xyz, noise_ctx);
    k_knn_own<0><<<dim3(NCTX / 192, BB), 192>>>();
    k_knn_screen<0><<<dim3(NCTX / 12, BB), 128>>>();
    k_knn_refine<0><<<NC_TOT / 256, 256>>>();
    k_wab<<<(131 * 128 + 255) / 256, 256>>>(We1, be1);
    k_proj<0><<<BB * PP / 8, 128>>>(ctx_tokens, Wp, bp);
    k_anchor<<<BB, 128>>>(ctx_xyz);
    k_xyz_pred<<<NP_TOT / 128, 128>>>(noise_pred);
    k_proj<1><<<BB * MMH / 8, 128>>>(pred_tokens, Wp, bp);

    // ---- context branch ----
    k_ab<0><<<NC_TOT / 16, 256>>>();
    k_edge<0><<<NC_TOT / 8, 128>>>(We2, be2);
    k_offset<0><<<NC_TOT / 8, 128>>>(Wc1, bc1, Wc2, bc2, nullptr);

    // ---- prediction branch ----
    k_knn_pred<<<NP_TOT / 128, 128>>>();
    k_ab<1><<<NP_TOT / 16, 256>>>();
    k_edge<1><<<NP_TOT / 8, 128>>>(We2, be2);
    k_offset<1><<<NP_TOT / 8, 128>>>(Wq1, bq1, Wq2, bq2, nullptr);

    // ---- global refinement ----
    k_knn_own<2><<<dim3(NALL / 192, BB), 192>>>();
    k_knn_screen<2><<<dim3(NALL / 12, BB), 128>>>();
    k_knn_refine<2><<<NA_TOT / 256, 256>>>();
    k_ab<2><<<NA_TOT / 16, 256>>>();
    k_edge<2><<<NA_TOT / 8, 128>>>(We2, be2);
    k_offset<2><<<NA_TOT / 8, 128>>>(Wf1, bf1, Wf2, bf2, out);
}

// round 17
// speedup vs baseline: 1.4463x; 1.0348x over previous
#include <cuda_runtime.h>

// ---------------------------------------------------------------------------
// JEPAPointDecoder — full pipeline on GB300, fp32 with packed f32x2 FMA.
//
// Shapes: B=4, P=384, M=64, TOK=1024, C=128, R=12, k=8
//
// EdgeConv layer-1 factorization:  msg@We1 = a_i + b_j  with
//   a_i = x_i @ (We1_top - We1_bot) + be1,   b_j = x_j @ We1_bot
//
// kNN: exact cluster-screened (12-replica clusters; own-cluster bound +
// triangle-inequality screen with conservative fp margins; refinement with
// bit-identical reference d2 and lex (ordered-d2, idx) keys).
//
// R17: k_ab parent factorization for ctx/pred stages — the feature half of
// [a|b] is identical across a parent's 12 replicas, so it is computed once
// per parent (k_abf) and combined with the per-point xyz half (k_ab_pt)
// using the exact same parse tree ((u.x+u.y)+tacc) -> bitwise identical.
// ---------------------------------------------------------------------------

#define BB     4
#define PP     384
#define MMH    64
#define TOKN   1024
#define CC     128
#define RR     12
#define KK     8
#define NCTX   (PP*RR)        // 4608
#define NPRED  (MMH*RR)       // 768
#define NALL   (NCTX+NPRED)   // 5376
#define NC_TOT (BB*NCTX)      // 18432
#define NP_TOT (BB*NPRED)     // 3072
#define NA_TOT (BB*NALL)      // 21504
#define NCLMAX (NALL/12)      // 448 clusters per batch (global stage)
#define CAP    120            // cluster-list capacity (overflow -> fallback)

// ----------------------------- scratch ------------------------------------
__device__ float g_anchor[BB*3];
__device__ float g_ctx_feat[BB*PP*CC];
__device__ float g_pred_feat[BB*MMH*CC];
__device__ float g_xyz_ctx[NC_TOT*3];
__device__ float g_xyz_p[NP_TOT*3];
__device__ float g_xyz_all[NA_TOT*3];
__device__ float g_featAll[(size_t)NA_TOT*CC];
__device__ float g_a[(size_t)NA_TOT*CC];
__device__ float g_b[(size_t)NA_TOT*CC];
__device__ int   g_idx[NA_TOT*KK];
__device__ float g_WabT[256*132];     // transposed: [col][r], r-pad 132
__device__ float g_bab[256];
__device__ float g_af[BB*PP*256];     // per-parent feature half of [a|b]

typedef unsigned long long u64;
__device__ u64   g_keys[(size_t)NA_TOT*8];      // per-query top-8 lex keys
__device__ float g_ccen[BB*NCLMAX*3];
__device__ float g_crad[BB*NCLMAX];
__device__ float g_crq[BB*NCLMAX];
__device__ int   g_ccnt[BB*NCLMAX];
__device__ int   g_clist[BB*NCLMAX*CAP];

// --------------------------- f32x2 primitives ------------------------------
__device__ __forceinline__ void ffma2(u64& d, u64 a, u64 b) {
    asm("fma.rn.f32x2 %0, %1, %2, %0;" : "+l"(d) : "l"(a), "l"(b));
}
__device__ __forceinline__ u64 pack2(float lo, float hi) {
    u64 r;
    unsigned int a = __float_as_uint(lo), b = __float_as_uint(hi);
    asm("mov.b64 %0, {%1, %2};" : "=l"(r) : "r"(a), "r"(b));
    return r;
}
__device__ __forceinline__ float2 unpack2(u64 v) {
    unsigned int a, b;
    asm("mov.b64 {%0, %1}, %2;" : "=r"(a), "=r"(b) : "l"(v));
    return make_float2(__uint_as_float(a), __uint_as_float(b));
}

// ----------------------------- helpers ------------------------------------
template<int MODE>
__device__ __forceinline__ int mapOut(int i) {
    if (MODE == 0) return (i / NCTX)  * NALL + (i % NCTX);           // ctx
    if (MODE == 1) return (i / NPRED) * NALL + NCTX + (i % NPRED);   // pred
    return i;                                                        // global
}

__device__ __forceinline__ float sq3(float x, float y, float z) {
    return __fadd_rn(__fadd_rn(__fmul_rn(x, x), __fmul_rn(y, y)), __fmul_rn(z, z));
}

// order-preserving float->uint (monotone; -0 cannot occur for our d2)
__device__ __forceinline__ unsigned int ordf(float f) {
    unsigned int b = __float_as_uint(f);
    return (b & 0x80000000u) ? ~b : (b | 0x80000000u);
}
__device__ __forceinline__ float iordf(unsigned int h) {
    unsigned int b = (h & 0x80000000u) ? (h & 0x7FFFFFFFu) : ~h;
    return __uint_as_float(b);
}
__device__ __forceinline__ u64 dkey(float d2, int j) {
    return ((u64)ordf(d2) << 32) | (unsigned int)j;
}
// exact reference d2: sub(add(qw,pw), mul(2,dot)), dot = mul,fma,fma
__device__ __forceinline__ float refd2(float qx, float qy, float qz, float qw,
                                       float px, float py, float pz, float pw) {
    float dot = __fmul_rn(qx, px);
    dot = __fmaf_rn(qy, py, dot);
    dot = __fmaf_rn(qz, pz, dot);
    return __fsub_rn(__fadd_rn(qw, pw), __fmul_rn(2.0f, dot));
}
// sorted strict-< insert of key into ascending k[0..7]
#define KEY_INS(k, key) do {                                            \
    if ((key) < k[7]) {                                                 \
        int _pos = 7;                                                   \
        _Pragma("unroll")                                               \
        for (int _s = 7; _s > 0; --_s)                                  \
            if ((key) < k[_s - 1]) { k[_s] = k[_s - 1]; _pos = _s - 1; }\
        k[_pos] = (key);                                                \
    } } while (0)

// ----------------------------- anchors ------------------------------------
__global__ void k_anchor(const float* __restrict__ ctx_xyz) {
    int b = blockIdx.x, tid = threadIdx.x;
    __shared__ float sred[3][128];
    float sx = 0.f, sy = 0.f, sz = 0.f;
    for (int p = tid; p < PP; p += 128) {
        const float* q = &ctx_xyz[(b * PP + p) * 3];
        sx += q[0]; sy += q[1]; sz += q[2];
    }
    sred[0][tid] = sx; sred[1][tid] = sy; sred[2][tid] = sz;
    __syncthreads();
    for (int s = 64; s > 0; s >>= 1) {
        if (tid < s) {
            sred[0][tid] += sred[0][tid + s];
            sred[1][tid] += sred[1][tid + s];
            sred[2][tid] += sred[2][tid + s];
        }
        __syncthreads();
    }
    if (tid == 0) {
        g_anchor[b * 3 + 0] = __fdiv_rn(sred[0][0], (float)PP);
        g_anchor[b * 3 + 1] = __fdiv_rn(sred[1][0], (float)PP);
        g_anchor[b * 3 + 2] = __fdiv_rn(sred[2][0], (float)PP);
    }
}

// --------------------------- token projection -----------------------------
template<int WHICH>
__global__ void k_proj(const float* __restrict__ tokens,
                       const float* __restrict__ Wp,
                       const float* __restrict__ bp) {
    constexpr int RPB = 8;
    __shared__ __align__(16) float st[RPB * TOKN];        // 32 KB
    float* out = (WHICH == 0) ? g_ctx_feat : g_pred_feat;
    int r0 = blockIdx.x * RPB;
    for (int e = threadIdx.x; e < RPB * TOKN; e += 128)
        st[e] = tokens[(size_t)r0 * TOKN + e];
    __syncthreads();
    int c = threadIdx.x;
    float bb = bp[c];
    u64 acc[RPB];
#pragma unroll
    for (int r = 0; r < RPB; ++r) acc[r] = pack2(bb, 0.f);
    for (int t = 0; t < TOKN; t += 4) {
        float w0 = Wp[(t + 0) * CC + c];
        float w1 = Wp[(t + 1) * CC + c];
        float w2 = Wp[(t + 2) * CC + c];
        float w3 = Wp[(t + 3) * CC + c];
        u64 ww01 = pack2(w0, w1);
        u64 ww23 = pack2(w2, w3);
#pragma unroll
        for (int r = 0; r < RPB; ++r) {
            ulonglong2 v = *(const ulonglong2*)&st[r * TOKN + t];
            ffma2(acc[r], v.x, ww01);
            ffma2(acc[r], v.y, ww23);
        }
    }
#pragma unroll
    for (int r = 0; r < RPB; ++r) {
        float2 u = unpack2(acc[r]);
        out[(size_t)(r0 + r) * CC + c] = u.x + u.y;
    }
}

// --------------------------- Wab construction (transposed) -----------------
__global__ void k_wab(const float* __restrict__ We1, const float* __restrict__ be1) {
    int t = blockIdx.x * 256 + threadIdx.x;
    if (t < 131 * 128) {
        int r = t >> 7, c = t & 127;
        float top = We1[r * CC + c];
        float bot = We1[(131 + r) * CC + c];
        g_WabT[c * 132 + r]         = __fsub_rn(top, bot);
        g_WabT[(128 + c) * 132 + r] = bot;
    }
    if (t < 128) { g_bab[t] = be1[t]; g_bab[128 + t] = 0.f; }
}

// ------------------------------ xyz builders ------------------------------
__global__ void k_xyz_ctx(const float* __restrict__ ctx_xyz,
                          const float* __restrict__ noise) {
    int i = blockIdx.x * 128 + threadIdx.x;
    if (i >= NC_TOT) return;
    float nx = noise[i * 3 + 0], ny = noise[i * 3 + 1], nz = noise[i * 3 + 2];
    float denom = __fadd_rn(sqrtf(sq3(nx, ny, nz)), 1e-6f);
    int bp = i / RR;
    g_xyz_ctx[i * 3 + 0] = __fadd_rn(ctx_xyz[bp * 3 + 0], __fmul_rn(__fdiv_rn(nx, denom), 0.02f));
    g_xyz_ctx[i * 3 + 1] = __fadd_rn(ctx_xyz[bp * 3 + 1], __fmul_rn(__fdiv_rn(ny, denom), 0.02f));
    g_xyz_ctx[i * 3 + 2] = __fadd_rn(ctx_xyz[bp * 3 + 2], __fmul_rn(__fdiv_rn(nz, denom), 0.02f));
}

__global__ void k_xyz_pred(const float* __restrict__ noise) {
    int i = blockIdx.x * 128 + threadIdx.x;
    if (i >= NP_TOT) return;
    float nx = noise[i * 3 + 0], ny = noise[i * 3 + 1], nz = noise[i * 3 + 2];
    float denom = __fadd_rn(sqrtf(sq3(nx, ny, nz)), 1e-6f);
    int b = i / NPRED;
    g_xyz_p[i * 3 + 0] = __fadd_rn(g_anchor[b * 3 + 0], __fmul_rn(__fdiv_rn(nx, denom), 0.05f));
    g_xyz_p[i * 3 + 1] = __fadd_rn(g_anchor[b * 3 + 1], __fmul_rn(__fdiv_rn(ny, denom), 0.05f));
    g_xyz_p[i * 3 + 2] = __fadd_rn(g_anchor[b * 3 + 2], __fmul_rn(__fdiv_rn(nz, denom), 0.05f));
}

// ===================== cluster-screened exact kNN ==========================
// kA: own-cluster top-8 + cluster center/radius/query-bound
template<int STAGE>  // 0: ctx, 2: global
__global__ void __launch_bounds__(192) k_knn_own() {
    constexpr int NB  = (STAGE == 0) ? NCTX : NALL;
    constexpr int NCL = NB / 12;
    const float* xyz = (STAGE == 0) ? g_xyz_ctx : g_xyz_all;
    __shared__ float4 spt[192];
    __shared__ float sbd[192];
    int b = blockIdx.y, tid = threadIdx.x;
    int i0 = blockIdx.x * 192;
    int i = i0 + tid;                 // batch-local query
    int base = b * NB;
    {
        float x = xyz[(base + i) * 3 + 0];
        float y = xyz[(base + i) * 3 + 1];
        float z = xyz[(base + i) * 3 + 2];
        spt[tid] = make_float4(x, y, z, sq3(x, y, z));
    }
    __syncthreads();
    int lc = tid / 12, r = tid - lc * 12;
    int lbase = lc * 12;
    float4 pq = spt[tid];
    u64 k[8];
#pragma unroll
    for (int s = 0; s < 8; ++s) k[s] = 0xFFFFFFFFFFFFFFFFull;
#pragma unroll
    for (int jj = 0; jj < 12; ++jj) {
        if (jj == r) continue;
        float4 pj = spt[lbase + jj];
        float d2 = refd2(pq.x, pq.y, pq.z, pq.w, pj.x, pj.y, pj.z, pj.w);
        u64 key = dkey(d2, i0 + lbase + jj);
        KEY_INS(k, key);
    }
    size_t kb = ((size_t)base + i) * 8;
#pragma unroll
    for (int s = 0; s < 8; ++s) g_keys[kb + s] = k[s];
    sbd[tid] = iordf((unsigned int)(k[7] >> 32));   // bd7 (11 cands >= 8: filled)
    __syncthreads();
    if (r == 0) {
        float mb = 0.f, sx = 0.f, sy = 0.f, sz = 0.f;
        for (int t = 0; t < 12; ++t) {
            mb = fmaxf(mb, sbd[lbase + t]);
            float4 p = spt[lbase + t];
            sx += p.x; sy += p.y; sz += p.z;
        }
        float cx = sx / 12.f, cy = sy / 12.f, cz = sz / 12.f;
        float mr2 = 0.f;
        for (int t = 0; t < 12; ++t) {
            float4 p = spt[lbase + t];
            float dx = p.x - cx, dy = p.y - cy, dz = p.z - cz;
            mr2 = fmaxf(mr2, dx * dx + dy * dy + dz * dz);
        }
        int cg = b * NCL + i / 12;
        g_ccen[cg * 3 + 0] = cx; g_ccen[cg * 3 + 1] = cy; g_ccen[cg * 3 + 2] = cz;
        g_crad[cg] = sqrtf(mr2) * 1.0001f + 1e-5f;
        g_crq[cg]  = sqrtf(fmaxf(mb, 0.f)) * 1.0001f + 1e-5f;
    }
}

// kB: conservative cluster-pair screen -> per-cluster candidate list
template<int STAGE>
__global__ void __launch_bounds__(128) k_knn_screen() {
    constexpr int NB  = (STAGE == 0) ? NCTX : NALL;
    constexpr int NCL = NB / 12;
    __shared__ int scnt;
    __shared__ int slist[CAP];
    int a = blockIdx.x, b = blockIdx.y;
    int cg = b * NCL + a;
    if (threadIdx.x == 0) scnt = 0;
    __syncthreads();
    float cx = g_ccen[cg * 3 + 0], cy = g_ccen[cg * 3 + 1], cz = g_ccen[cg * 3 + 2];
    float thr = g_crad[cg] + g_crq[cg] + 1e-4f;
    for (int c = threadIdx.x; c < NCL; c += 128) {
        if (c == a) continue;
        int og = b * NCL + c;
        float dx = cx - g_ccen[og * 3 + 0];
        float dy = cy - g_ccen[og * 3 + 1];
        float dz = cz - g_ccen[og * 3 + 2];
        float d2 = dx * dx + dy * dy + dz * dz;
        float lim = thr + g_crad[og];
        if (d2 < lim * lim) {
            int p = atomicAdd(&scnt, 1);
            if (p < CAP) slist[p] = c;
        }
    }
    __syncthreads();
    int n = scnt;
    if (threadIdx.x == 0) g_ccnt[cg] = (n > CAP) ? -1 : n;
    int nn = (n > CAP) ? 0 : n;
    for (int t = threadIdx.x; t < nn; t += 128)
        g_clist[(size_t)cg * CAP + t] = slist[t];
}

// kC: refine per query over candidate clusters (exact d2, lex keys).
template<int STAGE>
__global__ void __launch_bounds__(256) k_knn_refine() {
    constexpr int NB  = (STAGE == 0) ? NCTX : NALL;
    constexpr int NCL = NB / 12;
    const float* xyz = (STAGE == 0) ? g_xyz_ctx : g_xyz_all;
    int idx = blockIdx.x * 256 + threadIdx.x;       // grid covers NB*BB exactly
    int b = idx / NB, i = idx - b * NB;
    int base = b * NB;
    float qx = xyz[(base + i) * 3 + 0];
    float qy = xyz[(base + i) * 3 + 1];
    float qz = xyz[(base + i) * 3 + 2];
    float qw = sq3(qx, qy, qz);
    u64 k[8];
    size_t kb = ((size_t)base + i) * 8;
#pragma unroll
    for (int s = 0; s < 8; ++s) k[s] = g_keys[kb + s];
    int a = i / 12;
    int cg = b * NCL + a;
    int n = g_ccnt[cg];
    int nit = (n < 0) ? NCL : n;                    // fallback: all clusters
    for (int t = 0; t < nit; ++t) {
        int c;
        if (n < 0) { c = t; if (c == a) continue; }
        else         c = g_clist[(size_t)cg * CAP + t];
        int jb = c * 12;
#pragma unroll
        for (int jj = 0; jj < 12; ++jj) {
            int j = jb + jj;
            float px = xyz[(base + j) * 3 + 0];
            float py = xyz[(base + j) * 3 + 1];
            float pz = xyz[(base + j) * 3 + 2];
            float pw = sq3(px, py, pz);
            float d2 = refd2(qx, qy, qz, qw, px, py, pz, pw);
            u64 key = dkey(d2, j);
            KEY_INS(k, key);
        }
    }
#pragma unroll
    for (int s = 0; s < 8; ++s)
        g_idx[(base + i) * KK + s] = base + (int)(k[s] & 0xFFFFFFFFu);
}

// tiny 12-point graphs: one thread per query point (pred branch)
__global__ void k_knn_pred() {
    int i = blockIdx.x * 128 + threadIdx.x;
    if (i >= NP_TOT) return;
    int base = (i / RR) * RR;
    int lr = i - base;
    float qx = g_xyz_p[i * 3 + 0], qy = g_xyz_p[i * 3 + 1], qz = g_xyz_p[i * 3 + 2];
    float qsq = sq3(qx, qy, qz);
    float bd[KK]; int bi[KK];
#pragma unroll
    for (int s = 0; s < KK; ++s) { bd[s] = 3.0e38f; bi[s] = 0; }
    for (int j = 0; j < RR; ++j) {
        if (j == lr) continue;
        int jj = base + j;
        float px = g_xyz_p[jj * 3 + 0], py = g_xyz_p[jj * 3 + 1], pz = g_xyz_p[jj * 3 + 2];
        float psq = sq3(px, py, pz);
        float d2 = refd2(qx, qy, qz, qsq, px, py, pz, psq);
        if (d2 < bd[KK - 1]) {
            int pos = KK - 1;
#pragma unroll
            for (int s = KK - 1; s > 0; --s) {
                if (d2 < bd[s - 1]) { bd[s] = bd[s - 1]; bi[s] = bi[s - 1]; pos = s - 1; }
            }
            bd[pos] = d2; bi[pos] = j;
        }
    }
#pragma unroll
    for (int s = 0; s < KK; ++s)
        g_idx[i * KK + s] = base + bi[s];
}

// ------------------- per-PARENT feature half of [a|b] ----------------------
// af[parent][col] = bias-init packed accumulation over feat rows 0..127,
// finalized as u.x + u.y — exactly the feature part of the old k_ab.
template<int WHICH>   // 0: ctx parents (BB*PP), 1: pred parents (BB*MMH)
__global__ void k_abf() {
    constexpr int PTS = 16;
    __shared__ __align__(16) float sx[PTS][CC];
    const float* feat = (WHICH == 0) ? g_ctx_feat : g_pred_feat;
    int p0 = blockIdx.x * PTS;
    for (int e = threadIdx.x; e < PTS * CC; e += 256)
        sx[e >> 7][e & 127] = feat[(size_t)p0 * CC + e];
    __syncthreads();
    int col = threadIdx.x;                // 0..255
    float bb = g_bab[col];
    u64 acc[PTS];
    u64 init = pack2(bb, 0.f);
#pragma unroll
    for (int p = 0; p < PTS; ++p) acc[p] = init;
    const float* wt = &g_WabT[col * 132];
    for (int r = 0; r < 128; r += 4) {
        float4 wv = *(const float4*)&wt[r];
        u64 ww01 = pack2(wv.x, wv.y);
        u64 ww23 = pack2(wv.z, wv.w);
#pragma unroll
        for (int p = 0; p < PTS; ++p) {
            ulonglong2 v = *(const ulonglong2*)&sx[p][r];
            ffma2(acc[p], v.x, ww01);
            ffma2(acc[p], v.y, ww23);
        }
    }
#pragma unroll
    for (int p = 0; p < PTS; ++p) {
        float2 u = unpack2(acc[p]);
        g_af[(size_t)(p0 + p) * 256 + col] = u.x + u.y;
    }
}

// --------------- per-point combine: af[parent] + xyz rows ------------------
// res = af + fmaf(z,w130, fmaf(y,w129, fmaf(x,w128, 0))) — same parse tree
// as the old k_ab's (u.x+u.y)+tacc -> bitwise identical results.
template<int MODE>   // 0 ctx, 1 pred
__global__ void __launch_bounds__(256) k_ab_pt() {
    constexpr int PTS = 16;
    __shared__ float sxyz[PTS][3];
    const float* xyz = (MODE == 0) ? g_xyz_ctx : g_xyz_p;
    int i0 = blockIdx.x * PTS;
    if (threadIdx.x < PTS * 3) {
        int p = threadIdx.x / 3, c = threadIdx.x - p * 3;
        sxyz[p][c] = xyz[(i0 + p) * 3 + c];
    }
    __syncthreads();
    int col = threadIdx.x;
    const float* wt = &g_WabT[col * 132];
    float w0 = wt[128], w1 = wt[129], w2 = wt[130];
#pragma unroll
    for (int p = 0; p < PTS; ++p) {
        int i = i0 + p;
        int par = i / RR;
        float af = g_af[(size_t)par * 256 + col];
        float t = fmaf(sxyz[p][0], w0, 0.f);
        t = fmaf(sxyz[p][1], w1, t);
        t = fmaf(sxyz[p][2], w2, t);
        float res = af + t;
        if (col < CC) g_a[(size_t)i * CC + col] = res;
        else          g_b[(size_t)i * CC + (col - CC)] = res;
    }
}

// ------------------------- full k_ab (global stage) ------------------------
template<int MODE>   // instantiated with 2 only
__global__ void k_ab() {
    constexpr int PTS = 16;
    __shared__ __align__(16) float sx[PTS][132];
    const float* feat = g_featAll;
    const float* xyz  = g_xyz_all;
    int i0 = blockIdx.x * PTS;
    for (int e = threadIdx.x; e < PTS * 131; e += 256) {
        int p = e / 131, t = e - p * 131;
        int i = i0 + p;
        sx[p][t] = (t < CC) ? feat[(size_t)i * CC + t] : xyz[i * 3 + (t - CC)];
    }
    __syncthreads();
    int col = threadIdx.x;                // 0..255
    float bb = g_bab[col];
    u64 acc[PTS];
    float tacc[PTS];
    u64 init = pack2(bb, 0.f);
#pragma unroll
    for (int p = 0; p < PTS; ++p) { acc[p] = init; tacc[p] = 0.f; }
    const float* wt = &g_WabT[col * 132];
    for (int r = 0; r < 128; r += 4) {
        float4 wv = *(const float4*)&wt[r];
        u64 ww01 = pack2(wv.x, wv.y);
        u64 ww23 = pack2(wv.z, wv.w);
#pragma unroll
        for (int p = 0; p < PTS; ++p) {
            ulonglong2 v = *(const ulonglong2*)&sx[p][r];
            ffma2(acc[p], v.x, ww01);
            ffma2(acc[p], v.y, ww23);
        }
    }
#pragma unroll
    for (int r = 128; r < 131; ++r) {
        float w = wt[r];
#pragma unroll
        for (int p = 0; p < PTS; ++p) tacc[p] = fmaf(sx[p][r], w, tacc[p]);
    }
#pragma unroll
    for (int p = 0; p < PTS; ++p) {
        float2 u = unpack2(acc[p]);
        float res = u.x + u.y + tacc[p];
        int i = i0 + p;
        if (col < CC) g_a[(size_t)i * CC + col] = res;
        else          g_b[(size_t)i * CC + (col - CC)] = res;
    }
}

// --------------------- EdgeConv layer 2 + max aggregate --------------------
// 128 threads = 64 col-pairs x 2 edge-halves; each thread: 2 adjacent cols
// x 32 edges (acc 32 u64). Per h: 8 LDS.128 (broadcast) + 1 LDG.64 weights
// + 32 FFMA2.
template<int MODE>
__global__ void __launch_bounds__(128) k_edge(const float* __restrict__ We2,
                                              const float* __restrict__ be2) {
    constexpr int PTS = 8;                            // 64 edges / block
    __shared__ __align__(16) float shid[128 * 68];    // [h][e], stride 68
    int i0 = blockIdx.x * PTS;
    int tid = threadIdx.x;
    {   // build: thread owns h-row tid
        int h = tid;
#pragma unroll
        for (int p = 0; p < PTS; ++p) {
            int i = i0 + p;
            float av = g_a[(size_t)i * CC + h];
#pragma unroll
            for (int j = 0; j < KK; ++j) {
                int nb = g_idx[i * KK + j];
                float bv = g_b[(size_t)nb * CC + h];
                shid[h * 68 + p * KK + j] = fmaxf(__fadd_rn(av, bv), 0.f);
            }
        }
    }
    __syncthreads();
    int cs = tid & 63, eh = tid >> 6;    // col-slot (2 cols), edge-half (32 edges)
    int c0 = cs * 2;
    u64 acc[32];
#pragma unroll
    for (int e = 0; e < 32; ++e) acc[e] = 0ull;
#pragma unroll 2
    for (int h = 0; h < 128; ++h) {
        float2 wv = *(const float2*)&We2[h * CC + c0];
        u64 w0 = pack2(wv.x, wv.x);
        u64 w1 = pack2(wv.y, wv.y);
        const ulonglong2* hp = (const ulonglong2*)&shid[h * 68 + eh * 32];
#pragma unroll
        for (int e2 = 0; e2 < 8; ++e2) {
            ulonglong2 v = hp[e2];
            ffma2(acc[e2 * 2 + 0],      v.x, w0);
            ffma2(acc[e2 * 2 + 1],      v.y, w0);
            ffma2(acc[16 + e2 * 2 + 0], v.x, w1);
            ffma2(acc[16 + e2 * 2 + 1], v.y, w1);
        }
    }
    float2 bb = *(const float2*)&be2[c0];
#pragma unroll
    for (int p2 = 0; p2 < 4; ++p2) {                  // points eh*4 + p2
        float2 a0 = unpack2(acc[p2 * 4 + 0]);
        float2 a1 = unpack2(acc[p2 * 4 + 1]);
        float2 a2 = unpack2(acc[p2 * 4 + 2]);
        float2 a3 = unpack2(acc[p2 * 4 + 3]);
        float mx0 = fmaxf(fmaxf(fmaxf(a0.x, a0.y), fmaxf(a1.x, a1.y)),
                          fmaxf(fmaxf(a2.x, a2.y), fmaxf(a3.x, a3.y)));
        float2 b0 = unpack2(acc[16 + p2 * 4 + 0]);
        float2 b1 = unpack2(acc[16 + p2 * 4 + 1]);
        float2 b2 = unpack2(acc[16 + p2 * 4 + 2]);
        float2 b3 = unpack2(acc[16 + p2 * 4 + 3]);
        float mx1 = fmaxf(fmaxf(fmaxf(b0.x, b0.y), fmaxf(b1.x, b1.y)),
                          fmaxf(fmaxf(b2.x, b2.y), fmaxf(b3.x, b3.y)));
        int row = mapOut<MODE>(i0 + eh * 4 + p2);
        *(float2*)&g_featAll[(size_t)row * CC + c0] =
            make_float2(mx0 + bb.x, mx1 + bb.y);
    }
}

// ------------------------------ offset MLP ---------------------------------
template<int MODE>
__global__ void __launch_bounds__(128) k_offset(const float* __restrict__ W1,
                                                const float* __restrict__ b1,
                                                const float* __restrict__ W2,
                                                const float* __restrict__ b2,
                                                float* __restrict__ outp) {
    constexpr int PTS = 8;
    __shared__ __align__(16) float sf[PTS][CC];
    __shared__ float sh[PTS][CC];
    int i0 = blockIdx.x * PTS, tid = threadIdx.x;
#pragma unroll
    for (int p = 0; p < PTS; ++p)
        sf[p][tid] = g_featAll[(size_t)mapOut<MODE>(i0 + p) * CC + tid];
    __syncthreads();
    float bb = b1[tid];
    u64 acc[PTS];
    u64 init = pack2(bb, 0.f);
#pragma unroll
    for (int p = 0; p < PTS; ++p) acc[p] = init;
    for (int r = 0; r < CC; r += 2) {
        u64 ww = pack2(W1[(r + 0) * CC + tid], W1[(r + 1) * CC + tid]);
#pragma unroll
        for (int p = 0; p < PTS; ++p) {
            u64 v = *(const u64*)&sf[p][r];
            ffma2(acc[p], v, ww);
        }
    }
#pragma unroll
    for (int p = 0; p < PTS; ++p) {
        float2 u = unpack2(acc[p]);
        sh[p][tid] = fmaxf(u.x + u.y, 0.f);
    }
    __syncthreads();
    int wp0 = (tid >> 5) * 2, l = tid & 31;
#pragma unroll
    for (int t = 0; t < 2; ++t) {
        int wp = wp0 + t;
        int i = i0 + wp;
        float s0 = 0.f, s1 = 0.f, s2 = 0.f;
        for (int h = l; h < CC; h += 32) {
            float hv = sh[wp][h];
            s0 = fmaf(hv, W2[h * 3 + 0], s0);
            s1 = fmaf(hv, W2[h * 3 + 1], s1);
            s2 = fmaf(hv, W2[h * 3 + 2], s2);
        }
#pragma unroll
        for (int off = 16; off; off >>= 1) {
            s0 += __shfl_down_sync(0xffffffffu, s0, off);
            s1 += __shfl_down_sync(0xffffffffu, s1, off);
            s2 += __shfl_down_sync(0xffffffffu, s2, off);
        }
        if (l == 0) {
            const float* xin = (MODE == 0) ? g_xyz_ctx : (MODE == 1) ? g_xyz_p : g_xyz_all;
            float* orow;
            if (MODE == 2) orow = outp + (size_t)i * 3;
            else           orow = g_xyz_all + (size_t)mapOut<MODE>(i) * 3;
            orow[0] = xin[i * 3 + 0] + s0 + b2[0];
            orow[1] = xin[i * 3 + 1] + s1 + b2[1];
            orow[2] = xin[i * 3 + 2] + s2 + b2[2];
        }
    }
}

// ------------------------------- launcher ----------------------------------
extern "C" void kernel_launch(void* const* d_in, const int* in_sizes, int n_in,
                              void* d_out, int out_size) {
    const float* ctx_xyz     = (const float*)d_in[0];
    const float* ctx_tokens  = (const float*)d_in[1];
    const float* pred_tokens = (const float*)d_in[2];
    const float* noise_ctx   = (const float*)d_in[3];
    const float* noise_pred  = (const float*)d_in[4];
    const float* Wp  = (const float*)d_in[5];
    const float* bp  = (const float*)d_in[6];
    const float* We1 = (const float*)d_in[7];
    const float* be1 = (const float*)d_in[8];
    const float* We2 = (const float*)d_in[9];
    const float* be2 = (const float*)d_in[10];
    const float* Wc1 = (const float*)d_in[11];
    const float* bc1 = (const float*)d_in[12];
    const float* Wc2 = (const float*)d_in[13];
    const float* bc2 = (const float*)d_in[14];
    const float* Wq1 = (const float*)d_in[15];
    const float* bq1 = (const float*)d_in[16];
    const float* Wq2 = (const float*)d_in[17];
    const float* bq2 = (const float*)d_in[18];
    const float* Wf1 = (const float*)d_in[19];
    const float* bf1 = (const float*)d_in[20];
    const float* Wf2 = (const float*)d_in[21];
    const float* bf2 = (const float*)d_in[22];
    (void)in_sizes; (void)n_in; (void)out_size;
    float* out = (float*)d_out;

    // launch 4 == ncu-captured slot -> k_abf<0> (new kernel) this round
    k_wab<<<(131 * 128 + 255) / 256, 256>>>(We1, be1);              // 1
    k_proj<0><<<BB * PP / 8, 128>>>(ctx_tokens, Wp, bp);            // 2
    k_xyz_ctx<<<NC_TOT / 128, 128>>>(ctx_xyz, noise_ctx);           // 3
    k_abf<0><<<BB * PP / 16, 256>>>();                              // 4 (profiled)
    k_knn_own<0><<<dim3(NCTX / 192, BB), 192>>>();
    k_knn_screen<0><<<dim3(NCTX / 12, BB), 128>>>();
    k_knn_refine<0><<<NC_TOT / 256, 256>>>();
    k_anchor<<<BB, 128>>>(ctx_xyz);
    k_xyz_pred<<<NP_TOT / 128, 128>>>(noise_pred);
    k_proj<1><<<BB * MMH / 8, 128>>>(pred_tokens, Wp, bp);

    // ---- context branch ----
    k_ab_pt<0><<<NC_TOT / 16, 256>>>();
    k_edge<0><<<NC_TOT / 8, 128>>>(We2, be2);
    k_offset<0><<<NC_TOT / 8, 128>>>(Wc1, bc1, Wc2, bc2, nullptr);

    // ---- prediction branch ----
    k_knn_pred<<<NP_TOT / 128, 128>>>();
    k_abf<1><<<BB * MMH / 16, 256>>>();
    k_ab_pt<1><<<NP_TOT / 16, 256>>>();
    k_edge<1><<<NP_TOT / 8, 128>>>(We2, be2);
    k_offset<1><<<NP_TOT / 8, 128>>>(Wq1, bq1, Wq2, bq2, nullptr);

    // ---- global refinement ----
    k_knn_own<2><<<dim3(NALL / 192, BB), 192>>>();
    k_knn_screen<2><<<dim3(NALL / 12, BB), 128>>>();
    k_knn_refine<2><<<NA_TOT / 256, 256>>>();
    k_ab<2><<<NA_TOT / 16, 256>>>();
    k_edge<2><<<NA_TOT / 8, 128>>>(We2, be2);
    k_offset<2><<<NA_TOT / 8, 128>>>(Wf1, bf1, Wf2, bf2, out);
}